// round 1
// baseline (speedup 1.0000x reference)
#include <cuda_runtime.h>

// ---------------------------------------------------------------------------
// Scratch: device globals only (no dynamic allocation anywhere).
// ---------------------------------------------------------------------------
__device__ float g_act1[64 * 24 * 64 * 64];   // conv1 out (relu'd, then BN in place)
__device__ float g_act2[64 * 24 * 32 * 32];
__device__ float g_act3[64 * 24 * 16 * 16];
__device__ float g_act4[64 * 24 * 8 * 8];
__device__ float g_scale[24];
__device__ float g_shift[24];
__device__ float g_u[4096 * 256];             // (o @ Wi)   per (b,pos)
__device__ float g_v[4096 * 256];             // (o @ Wj)
__device__ float g_qb[64 * 256];              // qst @ Wq + gb1
__device__ float g_h2[262144 * 256];          // layer-2 activations
__device__ float g_h3[262144 * 256];          // layer-3 activations
__device__ float g_part[4096 * 128];          // layer-4 per-block column partial sums
__device__ float g_gsum[64 * 256];            // g = sum over pairs

// ---------------------------------------------------------------------------
// Conv (3x3, stride 2, pad 1) + bias + relu.  L selects layer (1..4).
// ---------------------------------------------------------------------------
template <int L>
__device__ __forceinline__ float* act_buf() {
    if constexpr (L == 1) return g_act1;
    else if constexpr (L == 2) return g_act2;
    else if constexpr (L == 3) return g_act3;
    else return g_act4;
}

template <int L>
__global__ void conv_kernel(const float* __restrict__ img,
                            const float* __restrict__ w,
                            const float* __restrict__ cb) {
    constexpr int CIN = (L == 1) ? 3 : 24;
    constexpr int H   = 256 >> L;   // input spatial (128,64,32,16)
    constexpr int OH  = 128 >> L;   // output spatial (64,32,16,8)
    constexpr int TOTAL = 64 * 24 * OH * OH;

    const float* in = (L == 1) ? img : act_buf<L - 1 + (L == 1 ? 1 : 0)>();
    // (for L==1 the ternary picks img; template arg unused there but must be valid)
    float* out = act_buf<L>();

    int idx = blockIdx.x * blockDim.x + threadIdx.x;
    if (idx >= TOTAL) return;
    int ow = idx % OH;
    int r  = idx / OH;
    int oh = r % OH;
    r /= OH;
    int co = r % 24;
    int b  = r / 24;

    float s = cb[co];
#pragma unroll
    for (int ci = 0; ci < CIN; ci++) {
        const float* ip = in + ((b * CIN + ci) * H) * H;
        const float* wp = w + (co * CIN + ci) * 9;
#pragma unroll
        for (int kh = 0; kh < 3; kh++) {
            int ih = oh * 2 - 1 + kh;
            if (ih < 0 || ih >= H) continue;
#pragma unroll
            for (int kw = 0; kw < 3; kw++) {
                int iw = ow * 2 - 1 + kw;
                if (iw < 0 || iw >= H) continue;
                s = fmaf(ip[ih * H + iw], wp[kh * 3 + kw], s);
            }
        }
    }
    out[idx] = fmaxf(s, 0.0f);
}

// ---------------------------------------------------------------------------
// BatchNorm: stats (mean/var over B,H,W per channel) then affine apply.
// ---------------------------------------------------------------------------
template <int L>
__global__ void bn_stats_kernel(const float* __restrict__ bg,
                                const float* __restrict__ bb) {
    constexpr int HW = (128 >> L) * (128 >> L);
    constexpr int N  = 64 * HW;
    const float* y = act_buf<L>();
    int c = blockIdx.x;
    int t = threadIdx.x;

    float s = 0.f, s2 = 0.f;
    for (int i = t; i < N; i += 256) {
        int b = i / HW;
        int p = i - b * HW;
        float v = y[(b * 24 + c) * HW + p];
        s += v;
        s2 += v * v;
    }
    __shared__ float rs[256], rq[256];
    rs[t] = s;
    rq[t] = s2;
    __syncthreads();
    for (int o = 128; o > 0; o >>= 1) {
        if (t < o) { rs[t] += rs[t + o]; rq[t] += rq[t + o]; }
        __syncthreads();
    }
    if (t == 0) {
        float m   = rs[0] / (float)N;
        float var = rq[0] / (float)N - m * m;
        float rst = rsqrtf(var + 1e-5f);
        g_scale[c] = rst * bg[c];
        g_shift[c] = bb[c] - m * rst * bg[c];
    }
}

template <int L>
__global__ void bn_apply_kernel() {
    constexpr int HW = (128 >> L) * (128 >> L);
    constexpr int TOTAL = 64 * 24 * HW;
    float* y = act_buf<L>();
    int idx = blockIdx.x * blockDim.x + threadIdx.x;
    if (idx >= TOTAL) return;
    int c = (idx / HW) % 24;
    y[idx] = fmaf(y[idx], g_scale[c], g_shift[c]);
}

// ---------------------------------------------------------------------------
// u = o @ Wi, v = o @ Wj  (o = [24 BN channels, row, col] per (b,pos)),
// qb = qst @ Wq + gb1.
// ---------------------------------------------------------------------------
__global__ void uv_kernel(const float* __restrict__ gw1) {
    int bp = blockIdx.x;         // 0..4095: b*64 + p
    int b  = bp >> 6;
    int p  = bp & 63;
    int t  = threadIdx.x;        // 256

    __shared__ float o[26];
    if (t < 24) o[t] = g_act4[(b * 24 + t) * 64 + p];
    else if (t == 24) o[24] = (float)(p >> 3);   // idx // H
    else if (t == 25) o[25] = (float)(p & 7);    // idx % W
    __syncthreads();

    float u = 0.f, v = 0.f;
#pragma unroll
    for (int c = 0; c < 26; c++) {
        float oc = o[c];
        u = fmaf(oc, gw1[c * 256 + t], u);
        v = fmaf(oc, gw1[(26 + c) * 256 + t], v);
    }
    g_u[bp * 256 + t] = u;
    g_v[bp * 256 + t] = v;
}

__global__ void qb_kernel(const float* __restrict__ qst,
                          const float* __restrict__ gw1,
                          const float* __restrict__ gb1) {
    int b = blockIdx.x;
    int t = threadIdx.x;
    __shared__ float q[11];
    if (t < 11) q[t] = qst[b * 11 + t];
    __syncthreads();
    float s = gb1[t];
#pragma unroll
    for (int k = 0; k < 11; k++) s = fmaf(q[k], gw1[(52 + k) * 256 + t], s);
    g_qb[b * 256 + t] = s;
}

// ---------------------------------------------------------------------------
// The big GEMMs.  Y[262144,256] = relu(X @ W + bias).
//   L==2: X computed on the fly: X[r,k] = relu(u[b,j,k] + v[b,i,k] + qb[b,k]),
//         r = ((b*64)+i)*64 + j.  Output -> g_h2.
//   L==3: X = g_h2, output -> g_h3.
//   L==4: X = g_h3, output reduced over the block's 128 rows -> g_part.
// 128x128 CTA tile, BK=16, 8x8 per-thread microtile, double-buffered smem.
// ---------------------------------------------------------------------------
template <int L>
__device__ __forceinline__ float4 load_x(int row, int k) {
    if constexpr (L == 2) {
        int b = row >> 12;
        int i = (row >> 6) & 63;
        int j = row & 63;
        float4 u = *reinterpret_cast<const float4*>(&g_u[((b << 6) + j) * 256 + k]);
        float4 v = *reinterpret_cast<const float4*>(&g_v[((b << 6) + i) * 256 + k]);
        float4 q = *reinterpret_cast<const float4*>(&g_qb[(b << 8) + k]);
        float4 r;
        r.x = fmaxf(u.x + v.x + q.x, 0.f);
        r.y = fmaxf(u.y + v.y + q.y, 0.f);
        r.z = fmaxf(u.z + v.z + q.z, 0.f);
        r.w = fmaxf(u.w + v.w + q.w, 0.f);
        return r;
    } else if constexpr (L == 3) {
        return *reinterpret_cast<const float4*>(&g_h2[(size_t)row * 256 + k]);
    } else {
        return *reinterpret_cast<const float4*>(&g_h3[(size_t)row * 256 + k]);
    }
}

template <int L>
__global__ void __launch_bounds__(256) gemm_kernel(const float* __restrict__ W,
                                                   const float* __restrict__ bias) {
    const int bid = blockIdx.x;
    const int bn  = bid & 1;       // which 128-col half of N=256
    const int bm  = bid >> 1;      // which 128-row block
    const int m0  = bm << 7;
    const int n0  = bn << 7;
    const int tid = threadIdx.x;
    const int ty  = tid >> 4;      // 0..15
    const int tx  = tid & 15;      // 0..15

    __shared__ float As[2][16][132];   // [k][m], padded
    __shared__ float Bs[2][16][128];   // [k][n]

    const int arow = tid >> 2;          // 0..63 (and +64)
    const int ak   = (tid & 3) << 2;    // 0,4,8,12
    const int brow = tid >> 5;          // 0..7 (and +8)
    const int bcol = (tid & 31) << 2;   // 0..124

    float acc[8][8];
#pragma unroll
    for (int i = 0; i < 8; i++)
#pragma unroll
        for (int j = 0; j < 8; j++) acc[i][j] = 0.f;

    // prologue: tile kt=0
    float4 fa0 = load_x<L>(m0 + arow, ak);
    float4 fa1 = load_x<L>(m0 + arow + 64, ak);
    float4 fb0 = *reinterpret_cast<const float4*>(&W[brow * 256 + n0 + bcol]);
    float4 fb1 = *reinterpret_cast<const float4*>(&W[(brow + 8) * 256 + n0 + bcol]);

    As[0][ak + 0][arow] = fa0.x; As[0][ak + 1][arow] = fa0.y;
    As[0][ak + 2][arow] = fa0.z; As[0][ak + 3][arow] = fa0.w;
    As[0][ak + 0][arow + 64] = fa1.x; As[0][ak + 1][arow + 64] = fa1.y;
    As[0][ak + 2][arow + 64] = fa1.z; As[0][ak + 3][arow + 64] = fa1.w;
    *reinterpret_cast<float4*>(&Bs[0][brow][bcol]) = fb0;
    *reinterpret_cast<float4*>(&Bs[0][brow + 8][bcol]) = fb1;
    __syncthreads();

    int cur = 0;
    for (int kt = 0; kt < 16; kt++) {
        if (kt < 15) {
            int k = (kt + 1) << 4;
            fa0 = load_x<L>(m0 + arow, k + ak);
            fa1 = load_x<L>(m0 + arow + 64, k + ak);
            fb0 = *reinterpret_cast<const float4*>(&W[(k + brow) * 256 + n0 + bcol]);
            fb1 = *reinterpret_cast<const float4*>(&W[(k + brow + 8) * 256 + n0 + bcol]);
        }
#pragma unroll
        for (int kk = 0; kk < 16; kk++) {
            float a[8], b[8];
            *reinterpret_cast<float4*>(&a[0]) =
                *reinterpret_cast<const float4*>(&As[cur][kk][ty << 3]);
            *reinterpret_cast<float4*>(&a[4]) =
                *reinterpret_cast<const float4*>(&As[cur][kk][(ty << 3) + 4]);
            *reinterpret_cast<float4*>(&b[0]) =
                *reinterpret_cast<const float4*>(&Bs[cur][kk][tx << 3]);
            *reinterpret_cast<float4*>(&b[4]) =
                *reinterpret_cast<const float4*>(&Bs[cur][kk][(tx << 3) + 4]);
#pragma unroll
            for (int i = 0; i < 8; i++)
#pragma unroll
                for (int j = 0; j < 8; j++)
                    acc[i][j] = fmaf(a[i], b[j], acc[i][j]);
        }
        int nxt = cur ^ 1;
        if (kt < 15) {
            As[nxt][ak + 0][arow] = fa0.x; As[nxt][ak + 1][arow] = fa0.y;
            As[nxt][ak + 2][arow] = fa0.z; As[nxt][ak + 3][arow] = fa0.w;
            As[nxt][ak + 0][arow + 64] = fa1.x; As[nxt][ak + 1][arow + 64] = fa1.y;
            As[nxt][ak + 2][arow + 64] = fa1.z; As[nxt][ak + 3][arow + 64] = fa1.w;
            *reinterpret_cast<float4*>(&Bs[nxt][brow][bcol]) = fb0;
            *reinterpret_cast<float4*>(&Bs[nxt][brow + 8][bcol]) = fb1;
        }
        __syncthreads();
        cur = nxt;
    }

    // bias for this thread's 8 columns
    float bv[8];
    *reinterpret_cast<float4*>(&bv[0]) =
        *reinterpret_cast<const float4*>(&bias[n0 + (tx << 3)]);
    *reinterpret_cast<float4*>(&bv[4]) =
        *reinterpret_cast<const float4*>(&bias[n0 + (tx << 3) + 4]);

    if constexpr (L != 4) {
        float* Y = (L == 2) ? g_h2 : g_h3;
#pragma unroll
        for (int i = 0; i < 8; i++) {
            int row = m0 + (ty << 3) + i;
            float o[8];
#pragma unroll
            for (int j = 0; j < 8; j++) o[j] = fmaxf(acc[i][j] + bv[j], 0.f);
            *reinterpret_cast<float4*>(&Y[(size_t)row * 256 + n0 + (tx << 3)]) =
                *reinterpret_cast<float4*>(&o[0]);
            *reinterpret_cast<float4*>(&Y[(size_t)row * 256 + n0 + (tx << 3) + 4]) =
                *reinterpret_cast<float4*>(&o[4]);
        }
    } else {
        // reduce the 128 rows of this block (all within one batch b = m0>>12)
        __shared__ float red[16][128];
        float cs[8];
#pragma unroll
        for (int j = 0; j < 8; j++) cs[j] = 0.f;
#pragma unroll
        for (int i = 0; i < 8; i++)
#pragma unroll
            for (int j = 0; j < 8; j++)
                cs[j] += fmaxf(acc[i][j] + bv[j], 0.f);
#pragma unroll
        for (int j = 0; j < 8; j++) red[ty][(tx << 3) + j] = cs[j];
        __syncthreads();
        if (tid < 128) {
            float s = 0.f;
#pragma unroll
            for (int r = 0; r < 16; r++) s += red[r][tid];
            g_part[bid * 128 + tid] = s;
        }
    }
}

// sum the 32 row-block partials per (batch, column) -> g
__global__ void reduce_g_kernel() {
    int b = blockIdx.x;       // 64
    int n = threadIdx.x;      // 256
    int nh = n >> 7;          // which 128-col half
    int nc = n & 127;
    float s = 0.f;
#pragma unroll
    for (int k = 0; k < 32; k++)
        s += g_part[(((b * 32 + k) * 2 + nh) << 7) + nc];
    g_gsum[b * 256 + n] = s;
}

// ---------------------------------------------------------------------------
// f-layers + softmax.  One block per batch row.
// ---------------------------------------------------------------------------
__global__ void f_kernel(const float* __restrict__ fw1, const float* __restrict__ fb1,
                         const float* __restrict__ fw2, const float* __restrict__ fb2,
                         const float* __restrict__ fw3, const float* __restrict__ fb3,
                         float* __restrict__ out) {
    int b = blockIdx.x;
    int t = threadIdx.x;   // 256
    __shared__ float s0[256], s1[256];
    __shared__ float lg[10];

    s0[t] = g_gsum[b * 256 + t];
    __syncthreads();

    float a = fb1[t];
    for (int c = 0; c < 256; c++) a = fmaf(s0[c], fw1[c * 256 + t], a);
    s1[t] = fmaxf(a, 0.f);
    __syncthreads();

    a = fb2[t];
    for (int c = 0; c < 256; c++) a = fmaf(s1[c], fw2[c * 256 + t], a);
    __syncthreads();
    s0[t] = fmaxf(a, 0.f);
    __syncthreads();

    if (t < 10) {
        float z = fb3[t];
        for (int c = 0; c < 256; c++) z = fmaf(s0[c], fw3[c * 10 + t], z);
        lg[t] = z;
    }
    __syncthreads();
    if (t == 0) {
        float mx = lg[0];
#pragma unroll
        for (int i = 1; i < 10; i++) mx = fmaxf(mx, lg[i]);
        float e[10];
        float ssum = 0.f;
#pragma unroll
        for (int i = 0; i < 10; i++) { e[i] = expf(lg[i] - mx); ssum += e[i]; }
        float inv = 1.0f / ssum;
#pragma unroll
        for (int i = 0; i < 10; i++) out[b * 10 + i] = e[i] * inv;
    }
}

// ---------------------------------------------------------------------------
// Launch
// ---------------------------------------------------------------------------
extern "C" void kernel_launch(void* const* d_in, const int* in_sizes, int n_in,
                              void* d_out, int out_size) {
    (void)in_sizes; (void)n_in; (void)out_size;
    const float* img = (const float*)d_in[0];
    const float* qst = (const float*)d_in[1];
    const float* cw1 = (const float*)d_in[2];
    const float* cb1 = (const float*)d_in[3];
    const float* bg1 = (const float*)d_in[4];
    const float* bb1 = (const float*)d_in[5];
    const float* cw2 = (const float*)d_in[6];
    const float* cb2 = (const float*)d_in[7];
    const float* bg2 = (const float*)d_in[8];
    const float* bb2 = (const float*)d_in[9];
    const float* cw3 = (const float*)d_in[10];
    const float* cb3 = (const float*)d_in[11];
    const float* bg3 = (const float*)d_in[12];
    const float* bb3 = (const float*)d_in[13];
    const float* cw4 = (const float*)d_in[14];
    const float* cb4 = (const float*)d_in[15];
    const float* bg4 = (const float*)d_in[16];
    const float* bb4 = (const float*)d_in[17];
    const float* gw1 = (const float*)d_in[18];
    const float* gb1 = (const float*)d_in[19];
    const float* gw2 = (const float*)d_in[20];
    const float* gb2 = (const float*)d_in[21];
    const float* gw3 = (const float*)d_in[22];
    const float* gb3 = (const float*)d_in[23];
    const float* gw4 = (const float*)d_in[24];
    const float* gb4 = (const float*)d_in[25];
    const float* fw1 = (const float*)d_in[26];
    const float* fb1 = (const float*)d_in[27];
    const float* fw2 = (const float*)d_in[28];
    const float* fb2 = (const float*)d_in[29];
    const float* fw3 = (const float*)d_in[30];
    const float* fb3 = (const float*)d_in[31];
    float* out = (float*)d_out;

    // conv stack
    conv_kernel<1><<<(64 * 24 * 64 * 64) / 256, 256>>>(img, cw1, cb1);
    bn_stats_kernel<1><<<24, 256>>>(bg1, bb1);
    bn_apply_kernel<1><<<(64 * 24 * 64 * 64) / 256, 256>>>();

    conv_kernel<2><<<(64 * 24 * 32 * 32) / 256, 256>>>(img, cw2, cb2);
    bn_stats_kernel<2><<<24, 256>>>(bg2, bb2);
    bn_apply_kernel<2><<<(64 * 24 * 32 * 32) / 256, 256>>>();

    conv_kernel<3><<<(64 * 24 * 16 * 16) / 256, 256>>>(img, cw3, cb3);
    bn_stats_kernel<3><<<24, 256>>>(bg3, bb3);
    bn_apply_kernel<3><<<(64 * 24 * 16 * 16) / 256, 256>>>();

    conv_kernel<4><<<(64 * 24 * 8 * 8) / 256, 256>>>(img, cw4, cb4);
    bn_stats_kernel<4><<<24, 256>>>(bg4, bb4);
    bn_apply_kernel<4><<<(64 * 24 * 8 * 8) / 256, 256>>>();

    // relation-network projections
    uv_kernel<<<4096, 256>>>(gw1);
    qb_kernel<<<64, 256>>>(qst, gw1, gb1);

    // relation MLP (h1 fused into layer-2 GEMM; layer-4 fuses the pair-sum)
    gemm_kernel<2><<<4096, 256>>>(gw2, gb2);
    gemm_kernel<3><<<4096, 256>>>(gw3, gb3);
    gemm_kernel<4><<<4096, 256>>>(gw4, gb4);
    reduce_g_kernel<<<64, 256>>>();

    // f-layers + softmax
    f_kernel<<<64, 256>>>(fw1, fb1, fw2, fb2, fw3, fb3, out);
}

// round 2
// speedup vs baseline: 1.0015x; 1.0015x over previous
#include <cuda_runtime.h>

// ---------------------------------------------------------------------------
// Scratch: device globals only (no dynamic allocation anywhere).
// ---------------------------------------------------------------------------
__device__ float g_act1[64 * 24 * 64 * 64];   // conv1 out (relu'd, then BN in place)
__device__ float g_act2[64 * 24 * 32 * 32];
__device__ float g_act3[64 * 24 * 16 * 16];
__device__ float g_act4[64 * 24 * 8 * 8];
__device__ float g_scale[24];
__device__ float g_shift[24];
__device__ float g_u[4096 * 256];             // (o @ Wi)   per (b,pos)
__device__ float g_v[4096 * 256];             // (o @ Wj)
__device__ float g_qb[64 * 256];              // qst @ Wq + gb1
__device__ float g_h2[262144 * 256];          // layer-2 activations
__device__ float g_h3[262144 * 256];          // layer-3 activations
__device__ float g_part[4096 * 128];          // layer-4 per-block column partial sums
__device__ float g_gsum[64 * 256];            // g = sum over pairs

// ---------------------------------------------------------------------------
// Conv (3x3, stride 2, pad 1) + bias + relu.  L selects layer (1..4).
// ---------------------------------------------------------------------------
template <int L>
__device__ __forceinline__ float* act_buf() {
    if constexpr (L == 1) return g_act1;
    else if constexpr (L == 2) return g_act2;
    else if constexpr (L == 3) return g_act3;
    else return g_act4;
}

template <int L>
__global__ void conv_kernel(const float* __restrict__ img,
                            const float* __restrict__ w,
                            const float* __restrict__ cb) {
    constexpr int CIN = (L == 1) ? 3 : 24;
    constexpr int H   = 256 >> L;   // input spatial (128,64,32,16)
    constexpr int OH  = 128 >> L;   // output spatial (64,32,16,8)
    constexpr int TOTAL = 64 * 24 * OH * OH;

    const float* in = (L == 1) ? img : act_buf<L - 1 + (L == 1 ? 1 : 0)>();
    // (for L==1 the ternary picks img; template arg unused there but must be valid)
    float* out = act_buf<L>();

    int idx = blockIdx.x * blockDim.x + threadIdx.x;
    if (idx >= TOTAL) return;
    int ow = idx % OH;
    int r  = idx / OH;
    int oh = r % OH;
    r /= OH;
    int co = r % 24;
    int b  = r / 24;

    float s = cb[co];
#pragma unroll
    for (int ci = 0; ci < CIN; ci++) {
        const float* ip = in + ((b * CIN + ci) * H) * H;
        const float* wp = w + (co * CIN + ci) * 9;
#pragma unroll
        for (int kh = 0; kh < 3; kh++) {
            int ih = oh * 2 - 1 + kh;
            if (ih < 0 || ih >= H) continue;
#pragma unroll
            for (int kw = 0; kw < 3; kw++) {
                int iw = ow * 2 - 1 + kw;
                if (iw < 0 || iw >= H) continue;
                s = fmaf(ip[ih * H + iw], wp[kh * 3 + kw], s);
            }
        }
    }
    out[idx] = fmaxf(s, 0.0f);
}

// ---------------------------------------------------------------------------
// BatchNorm: stats (mean/var over B,H,W per channel) then affine apply.
// ---------------------------------------------------------------------------
template <int L>
__global__ void bn_stats_kernel(const float* __restrict__ bg,
                                const float* __restrict__ bb) {
    constexpr int HW = (128 >> L) * (128 >> L);
    constexpr int N  = 64 * HW;
    const float* y = act_buf<L>();
    int c = blockIdx.x;
    int t = threadIdx.x;

    float s = 0.f, s2 = 0.f;
    for (int i = t; i < N; i += 256) {
        int b = i / HW;
        int p = i - b * HW;
        float v = y[(b * 24 + c) * HW + p];
        s += v;
        s2 += v * v;
    }
    __shared__ float rs[256], rq[256];
    rs[t] = s;
    rq[t] = s2;
    __syncthreads();
    for (int o = 128; o > 0; o >>= 1) {
        if (t < o) { rs[t] += rs[t + o]; rq[t] += rq[t + o]; }
        __syncthreads();
    }
    if (t == 0) {
        float m   = rs[0] / (float)N;
        float var = rq[0] / (float)N - m * m;
        float rst = rsqrtf(var + 1e-5f);
        g_scale[c] = rst * bg[c];
        g_shift[c] = bb[c] - m * rst * bg[c];
    }
}

template <int L>
__global__ void bn_apply_kernel() {
    constexpr int HW = (128 >> L) * (128 >> L);
    constexpr int TOTAL = 64 * 24 * HW;
    float* y = act_buf<L>();
    int idx = blockIdx.x * blockDim.x + threadIdx.x;
    if (idx >= TOTAL) return;
    int c = (idx / HW) % 24;
    y[idx] = fmaf(y[idx], g_scale[c], g_shift[c]);
}

// ---------------------------------------------------------------------------
// u = o @ Wi, v = o @ Wj  (o = [24 BN channels, row, col] per (b,pos)),
// qb = qst @ Wq + gb1.
// ---------------------------------------------------------------------------
__global__ void uv_kernel(const float* __restrict__ gw1) {
    int bp = blockIdx.x;         // 0..4095: b*64 + p
    int b  = bp >> 6;
    int p  = bp & 63;
    int t  = threadIdx.x;        // 256

    __shared__ float o[26];
    if (t < 24) o[t] = g_act4[(b * 24 + t) * 64 + p];
    else if (t == 24) o[24] = (float)(p >> 3);   // idx // H
    else if (t == 25) o[25] = (float)(p & 7);    // idx % W
    __syncthreads();

    float u = 0.f, v = 0.f;
#pragma unroll
    for (int c = 0; c < 26; c++) {
        float oc = o[c];
        u = fmaf(oc, gw1[c * 256 + t], u);
        v = fmaf(oc, gw1[(26 + c) * 256 + t], v);
    }
    g_u[bp * 256 + t] = u;
    g_v[bp * 256 + t] = v;
}

__global__ void qb_kernel(const float* __restrict__ qst,
                          const float* __restrict__ gw1,
                          const float* __restrict__ gb1) {
    int b = blockIdx.x;
    int t = threadIdx.x;
    __shared__ float q[11];
    if (t < 11) q[t] = qst[b * 11 + t];
    __syncthreads();
    float s = gb1[t];
#pragma unroll
    for (int k = 0; k < 11; k++) s = fmaf(q[k], gw1[(52 + k) * 256 + t], s);
    g_qb[b * 256 + t] = s;
}

// ---------------------------------------------------------------------------
// The big GEMMs.  Y[262144,256] = relu(X @ W + bias).
//   L==2: X computed on the fly: X[r,k] = relu(u[b,j,k] + v[b,i,k] + qb[b,k]),
//         r = ((b*64)+i)*64 + j.  Output -> g_h2.
//   L==3: X = g_h2, output -> g_h3.
//   L==4: X = g_h3, output reduced over the block's 128 rows -> g_part.
// 128x128 CTA tile, BK=16, 8x8 per-thread microtile, double-buffered smem.
// ---------------------------------------------------------------------------
template <int L>
__device__ __forceinline__ float4 load_x(int row, int k) {
    if constexpr (L == 2) {
        int b = row >> 12;
        int i = (row >> 6) & 63;
        int j = row & 63;
        float4 u = *reinterpret_cast<const float4*>(&g_u[((b << 6) + j) * 256 + k]);
        float4 v = *reinterpret_cast<const float4*>(&g_v[((b << 6) + i) * 256 + k]);
        float4 q = *reinterpret_cast<const float4*>(&g_qb[(b << 8) + k]);
        float4 r;
        r.x = fmaxf(u.x + v.x + q.x, 0.f);
        r.y = fmaxf(u.y + v.y + q.y, 0.f);
        r.z = fmaxf(u.z + v.z + q.z, 0.f);
        r.w = fmaxf(u.w + v.w + q.w, 0.f);
        return r;
    } else if constexpr (L == 3) {
        return *reinterpret_cast<const float4*>(&g_h2[(size_t)row * 256 + k]);
    } else {
        return *reinterpret_cast<const float4*>(&g_h3[(size_t)row * 256 + k]);
    }
}

template <int L>
__global__ void __launch_bounds__(256) gemm_kernel(const float* __restrict__ W,
                                                   const float* __restrict__ bias) {
    const int bid = blockIdx.x;
    const int bn  = bid & 1;       // which 128-col half of N=256
    const int bm  = bid >> 1;      // which 128-row block
    const int m0  = bm << 7;
    const int n0  = bn << 7;
    const int tid = threadIdx.x;
    const int ty  = tid >> 4;      // 0..15
    const int tx  = tid & 15;      // 0..15

    __shared__ float As[2][16][132];   // [k][m], padded
    __shared__ float Bs[2][16][128];   // [k][n]

    const int arow = tid >> 2;          // 0..63 (and +64)
    const int ak   = (tid & 3) << 2;    // 0,4,8,12
    const int brow = tid >> 5;          // 0..7 (and +8)
    const int bcol = (tid & 31) << 2;   // 0..124

    float acc[8][8];
#pragma unroll
    for (int i = 0; i < 8; i++)
#pragma unroll
        for (int j = 0; j < 8; j++) acc[i][j] = 0.f;

    // prologue: tile kt=0
    float4 fa0 = load_x<L>(m0 + arow, ak);
    float4 fa1 = load_x<L>(m0 + arow + 64, ak);
    float4 fb0 = *reinterpret_cast<const float4*>(&W[brow * 256 + n0 + bcol]);
    float4 fb1 = *reinterpret_cast<const float4*>(&W[(brow + 8) * 256 + n0 + bcol]);

    As[0][ak + 0][arow] = fa0.x; As[0][ak + 1][arow] = fa0.y;
    As[0][ak + 2][arow] = fa0.z; As[0][ak + 3][arow] = fa0.w;
    As[0][ak + 0][arow + 64] = fa1.x; As[0][ak + 1][arow + 64] = fa1.y;
    As[0][ak + 2][arow + 64] = fa1.z; As[0][ak + 3][arow + 64] = fa1.w;
    *reinterpret_cast<float4*>(&Bs[0][brow][bcol]) = fb0;
    *reinterpret_cast<float4*>(&Bs[0][brow + 8][bcol]) = fb1;
    __syncthreads();

    int cur = 0;
    for (int kt = 0; kt < 16; kt++) {
        if (kt < 15) {
            int k = (kt + 1) << 4;
            fa0 = load_x<L>(m0 + arow, k + ak);
            fa1 = load_x<L>(m0 + arow + 64, k + ak);
            fb0 = *reinterpret_cast<const float4*>(&W[(k + brow) * 256 + n0 + bcol]);
            fb1 = *reinterpret_cast<const float4*>(&W[(k + brow + 8) * 256 + n0 + bcol]);
        }
#pragma unroll
        for (int kk = 0; kk < 16; kk++) {
            float a[8], b[8];
            *reinterpret_cast<float4*>(&a[0]) =
                *reinterpret_cast<const float4*>(&As[cur][kk][ty << 3]);
            *reinterpret_cast<float4*>(&a[4]) =
                *reinterpret_cast<const float4*>(&As[cur][kk][(ty << 3) + 4]);
            *reinterpret_cast<float4*>(&b[0]) =
                *reinterpret_cast<const float4*>(&Bs[cur][kk][tx << 3]);
            *reinterpret_cast<float4*>(&b[4]) =
                *reinterpret_cast<const float4*>(&Bs[cur][kk][(tx << 3) + 4]);
#pragma unroll
            for (int i = 0; i < 8; i++)
#pragma unroll
                for (int j = 0; j < 8; j++)
                    acc[i][j] = fmaf(a[i], b[j], acc[i][j]);
        }
        int nxt = cur ^ 1;
        if (kt < 15) {
            As[nxt][ak + 0][arow] = fa0.x; As[nxt][ak + 1][arow] = fa0.y;
            As[nxt][ak + 2][arow] = fa0.z; As[nxt][ak + 3][arow] = fa0.w;
            As[nxt][ak + 0][arow + 64] = fa1.x; As[nxt][ak + 1][arow + 64] = fa1.y;
            As[nxt][ak + 2][arow + 64] = fa1.z; As[nxt][ak + 3][arow + 64] = fa1.w;
            *reinterpret_cast<float4*>(&Bs[nxt][brow][bcol]) = fb0;
            *reinterpret_cast<float4*>(&Bs[nxt][brow + 8][bcol]) = fb1;
        }
        __syncthreads();
        cur = nxt;
    }

    // bias for this thread's 8 columns
    float bv[8];
    *reinterpret_cast<float4*>(&bv[0]) =
        *reinterpret_cast<const float4*>(&bias[n0 + (tx << 3)]);
    *reinterpret_cast<float4*>(&bv[4]) =
        *reinterpret_cast<const float4*>(&bias[n0 + (tx << 3) + 4]);

    if constexpr (L != 4) {
        float* Y = (L == 2) ? g_h2 : g_h3;
#pragma unroll
        for (int i = 0; i < 8; i++) {
            int row = m0 + (ty << 3) + i;
            float o[8];
#pragma unroll
            for (int j = 0; j < 8; j++) o[j] = fmaxf(acc[i][j] + bv[j], 0.f);
            *reinterpret_cast<float4*>(&Y[(size_t)row * 256 + n0 + (tx << 3)]) =
                *reinterpret_cast<float4*>(&o[0]);
            *reinterpret_cast<float4*>(&Y[(size_t)row * 256 + n0 + (tx << 3) + 4]) =
                *reinterpret_cast<float4*>(&o[4]);
        }
    } else {
        // reduce the 128 rows of this block (all within one batch b = m0>>12)
        __shared__ float red[16][128];
        float cs[8];
#pragma unroll
        for (int j = 0; j < 8; j++) cs[j] = 0.f;
#pragma unroll
        for (int i = 0; i < 8; i++)
#pragma unroll
            for (int j = 0; j < 8; j++)
                cs[j] += fmaxf(acc[i][j] + bv[j], 0.f);
#pragma unroll
        for (int j = 0; j < 8; j++) red[ty][(tx << 3) + j] = cs[j];
        __syncthreads();
        if (tid < 128) {
            float s = 0.f;
#pragma unroll
            for (int r = 0; r < 16; r++) s += red[r][tid];
            g_part[bid * 128 + tid] = s;
        }
    }
}

// sum the 32 row-block partials per (batch, column) -> g
__global__ void reduce_g_kernel() {
    int b = blockIdx.x;       // 64
    int n = threadIdx.x;      // 256
    int nh = n >> 7;          // which 128-col half
    int nc = n & 127;
    float s = 0.f;
#pragma unroll
    for (int k = 0; k < 32; k++)
        s += g_part[(((b * 32 + k) * 2 + nh) << 7) + nc];
    g_gsum[b * 256 + n] = s;
}

// ---------------------------------------------------------------------------
// f-layers + softmax.  One block per batch row.
// ---------------------------------------------------------------------------
__global__ void f_kernel(const float* __restrict__ fw1, const float* __restrict__ fb1,
                         const float* __restrict__ fw2, const float* __restrict__ fb2,
                         const float* __restrict__ fw3, const float* __restrict__ fb3,
                         float* __restrict__ out) {
    int b = blockIdx.x;
    int t = threadIdx.x;   // 256
    __shared__ float s0[256], s1[256];
    __shared__ float lg[10];

    s0[t] = g_gsum[b * 256 + t];
    __syncthreads();

    float a = fb1[t];
    for (int c = 0; c < 256; c++) a = fmaf(s0[c], fw1[c * 256 + t], a);
    s1[t] = fmaxf(a, 0.f);
    __syncthreads();

    a = fb2[t];
    for (int c = 0; c < 256; c++) a = fmaf(s1[c], fw2[c * 256 + t], a);
    __syncthreads();
    s0[t] = fmaxf(a, 0.f);
    __syncthreads();

    if (t < 10) {
        float z = fb3[t];
        for (int c = 0; c < 256; c++) z = fmaf(s0[c], fw3[c * 10 + t], z);
        lg[t] = z;
    }
    __syncthreads();
    if (t == 0) {
        float mx = lg[0];
#pragma unroll
        for (int i = 1; i < 10; i++) mx = fmaxf(mx, lg[i]);
        float e[10];
        float ssum = 0.f;
#pragma unroll
        for (int i = 0; i < 10; i++) { e[i] = expf(lg[i] - mx); ssum += e[i]; }
        float inv = 1.0f / ssum;
#pragma unroll
        for (int i = 0; i < 10; i++) out[b * 10 + i] = e[i] * inv;
    }
}

// ---------------------------------------------------------------------------
// Launch
// ---------------------------------------------------------------------------
extern "C" void kernel_launch(void* const* d_in, const int* in_sizes, int n_in,
                              void* d_out, int out_size) {
    (void)in_sizes; (void)n_in; (void)out_size;
    const float* img = (const float*)d_in[0];
    const float* qst = (const float*)d_in[1];
    const float* cw1 = (const float*)d_in[2];
    const float* cb1 = (const float*)d_in[3];
    const float* bg1 = (const float*)d_in[4];
    const float* bb1 = (const float*)d_in[5];
    const float* cw2 = (const float*)d_in[6];
    const float* cb2 = (const float*)d_in[7];
    const float* bg2 = (const float*)d_in[8];
    const float* bb2 = (const float*)d_in[9];
    const float* cw3 = (const float*)d_in[10];
    const float* cb3 = (const float*)d_in[11];
    const float* bg3 = (const float*)d_in[12];
    const float* bb3 = (const float*)d_in[13];
    const float* cw4 = (const float*)d_in[14];
    const float* cb4 = (const float*)d_in[15];
    const float* bg4 = (const float*)d_in[16];
    const float* bb4 = (const float*)d_in[17];
    const float* gw1 = (const float*)d_in[18];
    const float* gb1 = (const float*)d_in[19];
    const float* gw2 = (const float*)d_in[20];
    const float* gb2 = (const float*)d_in[21];
    const float* gw3 = (const float*)d_in[22];
    const float* gb3 = (const float*)d_in[23];
    const float* gw4 = (const float*)d_in[24];
    const float* gb4 = (const float*)d_in[25];
    const float* fw1 = (const float*)d_in[26];
    const float* fb1 = (const float*)d_in[27];
    const float* fw2 = (const float*)d_in[28];
    const float* fb2 = (const float*)d_in[29];
    const float* fw3 = (const float*)d_in[30];
    const float* fb3 = (const float*)d_in[31];
    float* out = (float*)d_out;

    // conv stack
    conv_kernel<1><<<(64 * 24 * 64 * 64) / 256, 256>>>(img, cw1, cb1);
    bn_stats_kernel<1><<<24, 256>>>(bg1, bb1);
    bn_apply_kernel<1><<<(64 * 24 * 64 * 64) / 256, 256>>>();

    conv_kernel<2><<<(64 * 24 * 32 * 32) / 256, 256>>>(img, cw2, cb2);
    bn_stats_kernel<2><<<24, 256>>>(bg2, bb2);
    bn_apply_kernel<2><<<(64 * 24 * 32 * 32) / 256, 256>>>();

    conv_kernel<3><<<(64 * 24 * 16 * 16) / 256, 256>>>(img, cw3, cb3);
    bn_stats_kernel<3><<<24, 256>>>(bg3, bb3);
    bn_apply_kernel<3><<<(64 * 24 * 16 * 16) / 256, 256>>>();

    conv_kernel<4><<<(64 * 24 * 8 * 8) / 256, 256>>>(img, cw4, cb4);
    bn_stats_kernel<4><<<24, 256>>>(bg4, bb4);
    bn_apply_kernel<4><<<(64 * 24 * 8 * 8) / 256, 256>>>();

    // relation-network projections
    uv_kernel<<<4096, 256>>>(gw1);
    qb_kernel<<<64, 256>>>(qst, gw1, gb1);

    // relation MLP (h1 fused into layer-2 GEMM; layer-4 fuses the pair-sum)
    gemm_kernel<2><<<4096, 256>>>(gw2, gb2);
    gemm_kernel<3><<<4096, 256>>>(gw3, gb3);
    gemm_kernel<4><<<4096, 256>>>(gw4, gb4);
    reduce_g_kernel<<<64, 256>>>();

    // f-layers + softmax
    f_kernel<<<64, 256>>>(fw1, fb1, fw2, fb2, fw3, fb3, out);
}

// round 4
// speedup vs baseline: 1.0130x; 1.0114x over previous
#include <cuda_runtime.h>
#include <stdint.h>

// ===========================================================================
// Helpers
// ===========================================================================
__device__ __forceinline__ uint32_t smem_to_u32(const void* p) {
    uint32_t a;
    asm("{ .reg .u64 t; cvta.to.shared.u64 t, %1; cvt.u32.u64 %0, t; }" : "=r"(a) : "l"(p));
    return a;
}
__device__ __forceinline__ void cp_async16(uint32_t saddr, const void* gptr) {
    asm volatile("cp.async.cg.shared.global [%0], [%1], 16;" :: "r"(saddr), "l"(gptr));
}
#define CP_COMMIT() asm volatile("cp.async.commit_group;" ::: "memory")
#define CP_WAIT0()  asm volatile("cp.async.wait_group 0;" ::: "memory")

__device__ __forceinline__ float tf32r(float x) {
    uint32_t u;
    asm("cvt.rna.tf32.f32 %0, %1;" : "=r"(u) : "f"(x));
    return __uint_as_float(u);
}

// mma.sync m16n8k8 tf32 (row.col), D += A*B
__device__ __forceinline__ void mma8(float* d, const uint32_t* a, const uint32_t* b) {
    asm volatile(
        "mma.sync.aligned.m16n8k8.row.col.f32.tf32.tf32.f32 "
        "{%0,%1,%2,%3}, {%4,%5,%6,%7}, {%8,%9}, {%0,%1,%2,%3};"
        : "+f"(d[0]), "+f"(d[1]), "+f"(d[2]), "+f"(d[3])
        : "r"(a[0]), "r"(a[1]), "r"(a[2]), "r"(a[3]), "r"(b[0]), "r"(b[1]));
}

// ===========================================================================
// Scratch (device globals only)
// ===========================================================================
__device__ float g_act1[64 * 24 * 64 * 64];
__device__ float g_act2[64 * 24 * 32 * 32];
__device__ float g_act3[64 * 24 * 16 * 16];
__device__ float g_act4[64 * 24 * 8 * 8];
__device__ float g_scale[24];
__device__ float g_shift[24];
__device__ float g_u[4096 * 256];
__device__ float g_v[4096 * 256];
__device__ float g_qb[64 * 256];
__device__ float g_h2[262144 * 256];
__device__ float g_h3[262144 * 256];
__device__ float g_Wh[3][256 * 256];   // tf32 hi of gw2/gw3/gw4 ([k][n], no transpose)
__device__ float g_Wl[3][256 * 256];   // tf32 residual lo
__device__ float g_part[2048 * 256];
__device__ float g_gsum[64 * 256];

// ===========================================================================
// Conv (3x3, stride 2, pad 1) + bias + relu.  4-wide ow microtile.
// ===========================================================================
template <int L>
__device__ __forceinline__ float* act_buf() {
    if constexpr (L == 1) return g_act1;
    else if constexpr (L == 2) return g_act2;
    else if constexpr (L == 3) return g_act3;
    else return g_act4;
}

template <int L>
__global__ void conv_kernel(const float* __restrict__ img,
                            const float* __restrict__ w,
                            const float* __restrict__ cb) {
    constexpr int CIN = (L == 1) ? 3 : 24;
    constexpr int H   = 256 >> L;   // input spatial
    constexpr int OH  = 128 >> L;   // output spatial
    constexpr int OQ  = OH / 4;

    const float* in = (L == 1) ? img : act_buf<L - 1 + (L == 1 ? 1 : 0)>();
    float* out = act_buf<L>();

    int idx = blockIdx.x * blockDim.x + threadIdx.x;
    int ow0 = (idx % OQ) * 4;
    int r   = idx / OQ;
    int oh  = r % OH;
    r /= OH;
    int co = r % 24;
    int b  = r / 24;
    if (b >= 64) return;

    float s0 = cb[co], s1 = s0, s2 = s0, s3 = s0;
    const int iwb = ow0 * 2 - 1;

#pragma unroll
    for (int ci = 0; ci < CIN; ci++) {
        const float* ip = in + ((b * CIN + ci) * H) * H;
        const float* wp = w + (co * CIN + ci) * 9;
#pragma unroll
        for (int kh = 0; kh < 3; kh++) {
            int ih = oh * 2 - 1 + kh;
            if (ih < 0 || ih >= H) continue;
            const float* rp = ip + ih * H;
            float x[9];
#pragma unroll
            for (int t = 0; t < 9; t++) {
                int iw = iwb + t;
                x[t] = (iw >= 0 && iw < H) ? rp[iw] : 0.f;
            }
            float w0 = wp[kh * 3], w1 = wp[kh * 3 + 1], w2 = wp[kh * 3 + 2];
            s0 = fmaf(x[0], w0, fmaf(x[1], w1, fmaf(x[2], w2, s0)));
            s1 = fmaf(x[2], w0, fmaf(x[3], w1, fmaf(x[4], w2, s1)));
            s2 = fmaf(x[4], w0, fmaf(x[5], w1, fmaf(x[6], w2, s2)));
            s3 = fmaf(x[6], w0, fmaf(x[7], w1, fmaf(x[8], w2, s3)));
        }
    }
    float4 o;
    o.x = fmaxf(s0, 0.f); o.y = fmaxf(s1, 0.f);
    o.z = fmaxf(s2, 0.f); o.w = fmaxf(s3, 0.f);
    *reinterpret_cast<float4*>(&out[((b * 24 + co) * OH + oh) * OH + ow0]) = o;
}

// ===========================================================================
// BatchNorm
// ===========================================================================
template <int L>
__global__ void bn_stats_kernel(const float* __restrict__ bg,
                                const float* __restrict__ bb) {
    constexpr int HW = (128 >> L) * (128 >> L);
    constexpr int N  = 64 * HW;
    const float* y = act_buf<L>();
    int c = blockIdx.x;
    int t = threadIdx.x;

    float s = 0.f, s2 = 0.f;
    for (int i = t; i < N; i += 256) {
        int b = i / HW;
        int p = i - b * HW;
        float v = y[(b * 24 + c) * HW + p];
        s += v;
        s2 += v * v;
    }
    __shared__ float rs[256], rq[256];
    rs[t] = s;
    rq[t] = s2;
    __syncthreads();
    for (int o = 128; o > 0; o >>= 1) {
        if (t < o) { rs[t] += rs[t + o]; rq[t] += rq[t + o]; }
        __syncthreads();
    }
    if (t == 0) {
        float m   = rs[0] / (float)N;
        float var = rq[0] / (float)N - m * m;
        float rst = rsqrtf(var + 1e-5f);
        g_scale[c] = rst * bg[c];
        g_shift[c] = bb[c] - m * rst * bg[c];
    }
}

template <int L>
__global__ void bn_apply_kernel() {
    constexpr int HW = (128 >> L) * (128 >> L);
    constexpr int TOTAL = 64 * 24 * HW;
    float* y = act_buf<L>();
    int idx = blockIdx.x * blockDim.x + threadIdx.x;
    if (idx >= TOTAL) return;
    int c = (idx / HW) % 24;
    y[idx] = fmaf(y[idx], g_scale[c], g_shift[c]);
}

// ===========================================================================
// u/v/qb projections
// ===========================================================================
__global__ void uv_kernel(const float* __restrict__ gw1) {
    int bp = blockIdx.x;
    int b  = bp >> 6;
    int p  = bp & 63;
    int t  = threadIdx.x;

    __shared__ float o[26];
    if (t < 24) o[t] = g_act4[(b * 24 + t) * 64 + p];
    else if (t == 24) o[24] = (float)(p >> 3);
    else if (t == 25) o[25] = (float)(p & 7);
    __syncthreads();

    float u = 0.f, v = 0.f;
#pragma unroll
    for (int c = 0; c < 26; c++) {
        float oc = o[c];
        u = fmaf(oc, gw1[c * 256 + t], u);
        v = fmaf(oc, gw1[(26 + c) * 256 + t], v);
    }
    g_u[bp * 256 + t] = u;
    g_v[bp * 256 + t] = v;
}

__global__ void qb_kernel(const float* __restrict__ qst,
                          const float* __restrict__ gw1,
                          const float* __restrict__ gb1) {
    int b = blockIdx.x;
    int t = threadIdx.x;
    __shared__ float q[11];
    if (t < 11) q[t] = qst[b * 11 + t];
    __syncthreads();
    float s = gb1[t];
#pragma unroll
    for (int k = 0; k < 11; k++) s = fmaf(q[k], gw1[(52 + k) * 256 + t], s);
    g_qb[b * 256 + t] = s;
}

// ===========================================================================
// W split (hi/lo tf32), elementwise, [k][n] layout preserved
// ===========================================================================
__global__ void prep_w_kernel(const float* __restrict__ w2,
                              const float* __restrict__ w3,
                              const float* __restrict__ w4) {
    int L = blockIdx.y;
    const float* w = (L == 0) ? w2 : (L == 1) ? w3 : w4;
    int i = blockIdx.x * 256 + threadIdx.x;
    float x = w[i];
    float h = tf32r(x);
    g_Wh[L][i] = h;
    g_Wl[L][i] = tf32r(x - h);
}

// ===========================================================================
// tf32 mma.sync GEMM:  Y[M,256] = relu(X @ W + bias), 3-pass hi/lo split.
//   MODE 0: X = relu(u+v+qb) on the fly -> g_h2
//   MODE 1: X = g_h2 -> g_h3
//   MODE 2: X = g_h3 -> 128-row column sums -> g_part
// CTA 128x128 (grid 2048 x 2), 8 warps (2M x 4N), warp tile 64x32,
// K-chunks of 32, double-buffered smem, cp.async for B.
// ===========================================================================
// smem offsets (bytes)
static constexpr int AH_OFF = 0;                        // [2][128][36] f32
static constexpr int AL_OFF = 36864;
static constexpr int BH_OFF = 73728;                    // [2][32][132] f32
static constexpr int BL_OFF = 107520;
static constexpr int GEMM_SMEM = 141312;

template <int MODE>
__global__ void __launch_bounds__(256, 1) rn_gemm(const float* __restrict__ bias) {
    extern __shared__ char smem[];
    uint32_t* AHs = reinterpret_cast<uint32_t*>(smem + AH_OFF);
    uint32_t* ALs = reinterpret_cast<uint32_t*>(smem + AL_OFF);
    uint32_t* BHs = reinterpret_cast<uint32_t*>(smem + BH_OFF);
    uint32_t* BLs = reinterpret_cast<uint32_t*>(smem + BL_OFF);
    const uint32_t smem_b = smem_to_u32(smem);

    const int tid  = threadIdx.x;
    const int lane = tid & 31;
    const int wid  = tid >> 5;
    const int g    = lane >> 2;
    const int tig  = lane & 3;
    const int warpM = wid & 1;
    const int warpN = wid >> 1;
    const int m0 = blockIdx.x << 7;
    const int n0 = blockIdx.y << 7;

    // ---- A copy mapping: thread -> (row, 16 k's) ----
    const int arow  = tid >> 1;
    const int kbase = (tid & 1) << 4;
    const float *up = nullptr, *vp = nullptr, *qp = nullptr, *asrc = nullptr;
    if constexpr (MODE == 0) {
        int rg = m0 + arow;
        int b = rg >> 12, ii = (rg >> 6) & 63, jj = rg & 63;
        up = g_u + ((b << 6) + jj) * 256;
        vp = g_v + ((b << 6) + ii) * 256;
        qp = g_qb + (b << 8);
    } else {
        asrc = ((MODE == 1) ? g_h2 : g_h3) + (size_t)(m0 + arow) * 256;
    }

    // ---- B copy mapping: thread -> (k row, 16 n's) ----
    const float* Wh = g_Wh[MODE];
    const float* Wl = g_Wl[MODE];
    const int bk = tid >> 3;
    const int bn = (tid & 7) << 4;

    float acc[4][4][4];
#pragma unroll
    for (int i = 0; i < 4; i++)
#pragma unroll
        for (int j = 0; j < 4; j++)
#pragma unroll
            for (int e = 0; e < 4; e++) acc[i][j][e] = 0.f;

    float4 xs[4];   // A staging

    auto issueB = [&](int kt, int st) {
        const float* gh = Wh + (size_t)(kt * 32 + bk) * 256 + n0 + bn;
        const float* gl = Wl + (size_t)(kt * 32 + bk) * 256 + n0 + bn;
        uint32_t sh = smem_b + BH_OFF + ((st * 32 + bk) * 132 + bn) * 4;
        uint32_t sl = smem_b + BL_OFF + ((st * 32 + bk) * 132 + bn) * 4;
#pragma unroll
        for (int q = 0; q < 4; q++) {
            cp_async16(sh + q * 16, gh + 4 * q);
            cp_async16(sl + q * 16, gl + 4 * q);
        }
        CP_COMMIT();
    };
    auto loadA = [&](int kt) {
        int k0 = kt * 32 + kbase;
        if constexpr (MODE == 0) {
#pragma unroll
            for (int q = 0; q < 4; q++) {
                float4 uu = *reinterpret_cast<const float4*>(up + k0 + 4 * q);
                float4 vv = *reinterpret_cast<const float4*>(vp + k0 + 4 * q);
                float4 qq = *reinterpret_cast<const float4*>(qp + k0 + 4 * q);
                float4 x;
                x.x = fmaxf(uu.x + vv.x + qq.x, 0.f);
                x.y = fmaxf(uu.y + vv.y + qq.y, 0.f);
                x.z = fmaxf(uu.z + vv.z + qq.z, 0.f);
                x.w = fmaxf(uu.w + vv.w + qq.w, 0.f);
                xs[q] = x;
            }
        } else {
#pragma unroll
            for (int q = 0; q < 4; q++)
                xs[q] = *reinterpret_cast<const float4*>(asrc + k0 + 4 * q);
        }
    };
    auto storeA = [&](int st) {
        float* ah = reinterpret_cast<float*>(AHs) + (st * 128 + arow) * 36 + kbase;
        float* al = reinterpret_cast<float*>(ALs) + (st * 128 + arow) * 36 + kbase;
#pragma unroll
        for (int q = 0; q < 4; q++) {
            float4 x = xs[q];
            float4 h, l;
            h.x = tf32r(x.x); h.y = tf32r(x.y); h.z = tf32r(x.z); h.w = tf32r(x.w);
            l.x = tf32r(x.x - h.x); l.y = tf32r(x.y - h.y);
            l.z = tf32r(x.z - h.z); l.w = tf32r(x.w - h.w);
            *reinterpret_cast<float4*>(ah + 4 * q) = h;
            *reinterpret_cast<float4*>(al + 4 * q) = l;
        }
    };

    // prologue: chunk 0 -> stage 0
    issueB(0, 0);
    loadA(0);
    storeA(0);

    for (int kt = 0; kt < 8; kt++) {
        const int st = kt & 1;
        CP_WAIT0();
        __syncthreads();
        if (kt < 7) { issueB(kt + 1, st ^ 1); loadA(kt + 1); }

        // ---- compute on stage st ----
#pragma unroll
        for (int ks = 0; ks < 4; ks++) {
            const int k8 = ks * 8;
            uint32_t ah[4][4], al[4][4];
#pragma unroll
            for (int i = 0; i < 4; i++) {
                int r0 = warpM * 64 + i * 16 + g;
                int base = (st * 128 + r0) * 36 + k8 + tig;
                ah[i][0] = AHs[base];
                ah[i][1] = AHs[base + 8 * 36];
                ah[i][2] = AHs[base + 4];
                ah[i][3] = AHs[base + 8 * 36 + 4];
                al[i][0] = ALs[base];
                al[i][1] = ALs[base + 8 * 36];
                al[i][2] = ALs[base + 4];
                al[i][3] = ALs[base + 8 * 36 + 4];
            }
            uint32_t bh[4][2], bl[4][2];
#pragma unroll
            for (int j = 0; j < 4; j++) {
                int c0 = warpN * 32 + j * 8 + g;
                int base = (st * 32 + k8 + tig) * 132 + c0;
                bh[j][0] = BHs[base];
                bh[j][1] = BHs[base + 4 * 132];
                bl[j][0] = BLs[base];
                bl[j][1] = BLs[base + 4 * 132];
            }
#pragma unroll
            for (int i = 0; i < 4; i++)
#pragma unroll
                for (int j = 0; j < 4; j++) {
                    mma8(acc[i][j], ah[i], bh[j]);
                    mma8(acc[i][j], ah[i], bl[j]);
                    mma8(acc[i][j], al[i], bh[j]);
                }
        }
        if (kt < 7) storeA(st ^ 1);
    }

    // ---- epilogue ----
    if constexpr (MODE < 2) {
        float* Y = (MODE == 0) ? g_h2 : g_h3;
#pragma unroll
        for (int i = 0; i < 4; i++) {
            int r0 = m0 + warpM * 64 + i * 16 + g;
#pragma unroll
            for (int j = 0; j < 4; j++) {
                int c = n0 + warpN * 32 + j * 8 + 2 * tig;
                float b0 = bias[c], b1 = bias[c + 1];
                float2 v0, v1;
                v0.x = fmaxf(acc[i][j][0] + b0, 0.f);
                v0.y = fmaxf(acc[i][j][1] + b1, 0.f);
                v1.x = fmaxf(acc[i][j][2] + b0, 0.f);
                v1.y = fmaxf(acc[i][j][3] + b1, 0.f);
                *reinterpret_cast<float2*>(&Y[(size_t)r0 * 256 + c]) = v0;
                *reinterpret_cast<float2*>(&Y[(size_t)(r0 + 8) * 256 + c]) = v1;
            }
        }
    } else {
        __syncthreads();   // smem reuse for reduction
        float* red = reinterpret_cast<float*>(smem);   // [8][32]
#pragma unroll
        for (int j = 0; j < 4; j++) {
            int c = n0 + warpN * 32 + j * 8 + 2 * tig;
            float b0 = bias[c], b1 = bias[c + 1];
            float s0 = 0.f, s1 = 0.f;
#pragma unroll
            for (int i = 0; i < 4; i++) {
                s0 += fmaxf(acc[i][j][0] + b0, 0.f) + fmaxf(acc[i][j][2] + b0, 0.f);
                s1 += fmaxf(acc[i][j][1] + b1, 0.f) + fmaxf(acc[i][j][3] + b1, 0.f);
            }
#pragma unroll
            for (int m = 4; m <= 16; m <<= 1) {
                s0 += __shfl_xor_sync(0xffffffffu, s0, m);
                s1 += __shfl_xor_sync(0xffffffffu, s1, m);
            }
            if (lane < 4) {
                red[wid * 32 + j * 8 + 2 * tig]     = s0;
                red[wid * 32 + j * 8 + 2 * tig + 1] = s1;
            }
        }
        __syncthreads();
        if (tid < 128) {
            int c  = tid;
            int wn = c >> 5;
            float s = red[(2 * wn) * 32 + (c & 31)] + red[(2 * wn + 1) * 32 + (c & 31)];
            g_part[blockIdx.x * 256 + blockIdx.y * 128 + c] = s;
        }
    }
}

// g_gsum[b][n] = sum over the 32 row-tiles of batch b
__global__ void reduce_g_kernel() {
    int b = blockIdx.x;
    int t = threadIdx.x;
    float s = 0.f;
#pragma unroll
    for (int k = 0; k < 32; k++) s += g_part[(b * 32 + k) * 256 + t];
    g_gsum[b * 256 + t] = s;
}

// ===========================================================================
// f-layers + softmax
// ===========================================================================
__global__ void f_kernel(const float* __restrict__ fw1, const float* __restrict__ fb1,
                         const float* __restrict__ fw2, const float* __restrict__ fb2,
                         const float* __restrict__ fw3, const float* __restrict__ fb3,
                         float* __restrict__ out) {
    int b = blockIdx.x;
    int t = threadIdx.x;
    __shared__ float s0[256], s1[256];
    __shared__ float lg[10];

    s0[t] = g_gsum[b * 256 + t];
    __syncthreads();

    float a = fb1[t];
    for (int c = 0; c < 256; c++) a = fmaf(s0[c], fw1[c * 256 + t], a);
    s1[t] = fmaxf(a, 0.f);
    __syncthreads();

    a = fb2[t];
    for (int c = 0; c < 256; c++) a = fmaf(s1[c], fw2[c * 256 + t], a);
    __syncthreads();
    s0[t] = fmaxf(a, 0.f);
    __syncthreads();

    if (t < 10) {
        float z = fb3[t];
        for (int c = 0; c < 256; c++) z = fmaf(s0[c], fw3[c * 10 + t], z);
        lg[t] = z;
    }
    __syncthreads();
    if (t == 0) {
        float mx = lg[0];
#pragma unroll
        for (int i = 1; i < 10; i++) mx = fmaxf(mx, lg[i]);
        float e[10];
        float ssum = 0.f;
#pragma unroll
        for (int i = 0; i < 10; i++) { e[i] = expf(lg[i] - mx); ssum += e[i]; }
        float inv = 1.0f / ssum;
#pragma unroll
        for (int i = 0; i < 10; i++) out[b * 10 + i] = e[i] * inv;
    }
}

// ===========================================================================
// Launch
// ===========================================================================
extern "C" void kernel_launch(void* const* d_in, const int* in_sizes, int n_in,
                              void* d_out, int out_size) {
    (void)in_sizes; (void)n_in; (void)out_size;
    const float* img = (const float*)d_in[0];
    const float* qst = (const float*)d_in[1];
    const float* cw1 = (const float*)d_in[2];
    const float* cb1 = (const float*)d_in[3];
    const float* bg1 = (const float*)d_in[4];
    const float* bb1 = (const float*)d_in[5];
    const float* cw2 = (const float*)d_in[6];
    const float* cb2 = (const float*)d_in[7];
    const float* bg2 = (const float*)d_in[8];
    const float* bb2 = (const float*)d_in[9];
    const float* cw3 = (const float*)d_in[10];
    const float* cb3 = (const float*)d_in[11];
    const float* bg3 = (const float*)d_in[12];
    const float* bb3 = (const float*)d_in[13];
    const float* cw4 = (const float*)d_in[14];
    const float* cb4 = (const float*)d_in[15];
    const float* bg4 = (const float*)d_in[16];
    const float* bb4 = (const float*)d_in[17];
    const float* gw1 = (const float*)d_in[18];
    const float* gb1 = (const float*)d_in[19];
    const float* gw2 = (const float*)d_in[20];
    const float* gb2 = (const float*)d_in[21];
    const float* gw3 = (const float*)d_in[22];
    const float* gb3 = (const float*)d_in[23];
    const float* gw4 = (const float*)d_in[24];
    const float* gb4 = (const float*)d_in[25];
    const float* fw1 = (const float*)d_in[26];
    const float* fb1 = (const float*)d_in[27];
    const float* fw2 = (const float*)d_in[28];
    const float* fb2 = (const float*)d_in[29];
    const float* fw3 = (const float*)d_in[30];
    const float* fb3 = (const float*)d_in[31];
    float* out = (float*)d_out;

    static bool attr_done = false;
    if (!attr_done) {
        cudaFuncSetAttribute(rn_gemm<0>, cudaFuncAttributeMaxDynamicSharedMemorySize, GEMM_SMEM);
        cudaFuncSetAttribute(rn_gemm<1>, cudaFuncAttributeMaxDynamicSharedMemorySize, GEMM_SMEM);
        cudaFuncSetAttribute(rn_gemm<2>, cudaFuncAttributeMaxDynamicSharedMemorySize, GEMM_SMEM);
        attr_done = true;
    }

    // W split (independent)
    prep_w_kernel<<<dim3(256, 3), 256>>>(gw2, gw3, gw4);

    // conv stack
    conv_kernel<1><<<(64 * 24 * 64 * 64 / 4) / 256, 256>>>(img, cw1, cb1);
    bn_stats_kernel<1><<<24, 256>>>(bg1, bb1);
    bn_apply_kernel<1><<<(64 * 24 * 64 * 64) / 256, 256>>>();

    conv_kernel<2><<<(64 * 24 * 32 * 32 / 4) / 256, 256>>>(img, cw2, cb2);
    bn_stats_kernel<2><<<24, 256>>>(bg2, bb2);
    bn_apply_kernel<2><<<(64 * 24 * 32 * 32) / 256, 256>>>();

    conv_kernel<3><<<(64 * 24 * 16 * 16 / 4) / 256, 256>>>(img, cw3, cb3);
    bn_stats_kernel<3><<<24, 256>>>(bg3, bb3);
    bn_apply_kernel<3><<<(64 * 24 * 16 * 16) / 256, 256>>>();

    conv_kernel<4><<<(64 * 24 * 8 * 8 / 4) / 256, 256>>>(img, cw4, cb4);
    bn_stats_kernel<4><<<24, 256>>>(bg4, bb4);
    bn_apply_kernel<4><<<(64 * 24 * 8 * 8) / 256, 256>>>();

    // projections
    uv_kernel<<<4096, 256>>>(gw1);
    qb_kernel<<<64, 256>>>(qst, gw1, gb1);

    // relation MLP on tensor cores (legacy mma.sync tf32, 3-pass split)
    rn_gemm<0><<<dim3(2048, 2), 256, GEMM_SMEM>>>(gb2);
    rn_gemm<1><<<dim3(2048, 2), 256, GEMM_SMEM>>>(gb3);
    rn_gemm<2><<<dim3(2048, 2), 256, GEMM_SMEM>>>(gb4);
    reduce_g_kernel<<<64, 256>>>();

    // f-layers + softmax
    f_kernel<<<64, 256>>>(fw1, fb1, fw2, fb2, fw3, fb3, out);
}

// round 5
// speedup vs baseline: 1.4182x; 1.4000x over previous
#include <cuda_runtime.h>
#include <cuda_fp16.h>
#include <stdint.h>

// ===========================================================================
// Helpers
// ===========================================================================
__device__ __forceinline__ uint32_t smem_to_u32(const void* p) {
    uint32_t a;
    asm("{ .reg .u64 t; cvta.to.shared.u64 t, %1; cvt.u32.u64 %0, t; }" : "=r"(a) : "l"(p));
    return a;
}
__device__ __forceinline__ void cp_async16(uint32_t saddr, const void* gptr) {
    asm volatile("cp.async.cg.shared.global [%0], [%1], 16;" :: "r"(saddr), "l"(gptr));
}
#define CP_COMMIT() asm volatile("cp.async.commit_group;" ::: "memory")
#define CP_WAIT0()  asm volatile("cp.async.wait_group 0;" ::: "memory")

// ldmatrix x4 (four 8x8 b16 matrices)
__device__ __forceinline__ void ldx4(uint32_t* r, uint32_t addr) {
    asm volatile("ldmatrix.sync.aligned.m8n8.x4.shared.b16 {%0,%1,%2,%3}, [%4];"
                 : "=r"(r[0]), "=r"(r[1]), "=r"(r[2]), "=r"(r[3]) : "r"(addr));
}
// mma m16n8k16 f16 -> f32
__device__ __forceinline__ void mma16(float* d, const uint32_t* a, const uint32_t* b) {
    asm volatile(
        "mma.sync.aligned.m16n8k16.row.col.f32.f16.f16.f32 "
        "{%0,%1,%2,%3}, {%4,%5,%6,%7}, {%8,%9}, {%0,%1,%2,%3};"
        : "+f"(d[0]), "+f"(d[1]), "+f"(d[2]), "+f"(d[3])
        : "r"(a[0]), "r"(a[1]), "r"(a[2]), "r"(a[3]), "r"(b[0]), "r"(b[1]));
}
__device__ __forceinline__ uint32_t pack2(float a, float b) {
    __half2 h = __floats2half2_rn(a, b);
    return *reinterpret_cast<uint32_t*>(&h);
}
__device__ __forceinline__ void split2(float a, float b, uint32_t& hi, uint32_t& lo) {
    __half ha = __float2half_rn(a), hb = __float2half_rn(b);
    __half la = __float2half_rn(a - __half2float(ha));
    __half lb = __float2half_rn(b - __half2float(hb));
    __half2 h = __halves2half2(ha, hb), l = __halves2half2(la, lb);
    hi = *reinterpret_cast<uint32_t*>(&h);
    lo = *reinterpret_cast<uint32_t*>(&l);
}

// ===========================================================================
// Scratch (device globals only)
// ===========================================================================
__device__ float g_act1[64 * 24 * 64 * 64];
__device__ float g_act2[64 * 24 * 32 * 32];
__device__ float g_act3[64 * 24 * 16 * 16];
__device__ float g_act4[64 * 24 * 8 * 8];
__device__ float g_scale[24];
__device__ float g_shift[24];
__device__ float g_u[4096 * 256];
__device__ float g_v[4096 * 256];
__device__ float g_qb[64 * 256];
__device__ __half g_h2h[262144UL * 256], g_h2l[262144UL * 256];
__device__ __half g_h3h[262144UL * 256], g_h3l[262144UL * 256];
__device__ __half g_Wth[3][256 * 256];   // W^T hi plane, [n][k]
__device__ __half g_Wtl[3][256 * 256];   // W^T lo plane
__device__ float g_part[2048 * 256];
__device__ float g_gsum[64 * 256];

// ===========================================================================
// Conv (3x3, stride 2, pad 1) + bias + relu.  4-wide ow microtile.
// ===========================================================================
template <int L>
__device__ __forceinline__ float* act_buf() {
    if constexpr (L == 1) return g_act1;
    else if constexpr (L == 2) return g_act2;
    else if constexpr (L == 3) return g_act3;
    else return g_act4;
}

template <int L>
__global__ void conv_kernel(const float* __restrict__ img,
                            const float* __restrict__ w,
                            const float* __restrict__ cb) {
    constexpr int CIN = (L == 1) ? 3 : 24;
    constexpr int H   = 256 >> L;
    constexpr int OH  = 128 >> L;
    constexpr int OQ  = OH / 4;

    const float* in = (L == 1) ? img : act_buf<L - 1 + (L == 1 ? 1 : 0)>();
    float* out = act_buf<L>();

    int idx = blockIdx.x * blockDim.x + threadIdx.x;
    int ow0 = (idx % OQ) * 4;
    int r   = idx / OQ;
    int oh  = r % OH;
    r /= OH;
    int co = r % 24;
    int b  = r / 24;
    if (b >= 64) return;

    float s0 = cb[co], s1 = s0, s2 = s0, s3 = s0;
    const int iwb = ow0 * 2 - 1;

#pragma unroll
    for (int ci = 0; ci < CIN; ci++) {
        const float* ip = in + ((b * CIN + ci) * H) * H;
        const float* wp = w + (co * CIN + ci) * 9;
#pragma unroll
        for (int kh = 0; kh < 3; kh++) {
            int ih = oh * 2 - 1 + kh;
            if (ih < 0 || ih >= H) continue;
            const float* rp = ip + ih * H;
            float x[9];
#pragma unroll
            for (int t = 0; t < 9; t++) {
                int iw = iwb + t;
                x[t] = (iw >= 0 && iw < H) ? rp[iw] : 0.f;
            }
            float w0 = wp[kh * 3], w1 = wp[kh * 3 + 1], w2 = wp[kh * 3 + 2];
            s0 = fmaf(x[0], w0, fmaf(x[1], w1, fmaf(x[2], w2, s0)));
            s1 = fmaf(x[2], w0, fmaf(x[3], w1, fmaf(x[4], w2, s1)));
            s2 = fmaf(x[4], w0, fmaf(x[5], w1, fmaf(x[6], w2, s2)));
            s3 = fmaf(x[6], w0, fmaf(x[7], w1, fmaf(x[8], w2, s3)));
        }
    }
    float4 o;
    o.x = fmaxf(s0, 0.f); o.y = fmaxf(s1, 0.f);
    o.z = fmaxf(s2, 0.f); o.w = fmaxf(s3, 0.f);
    *reinterpret_cast<float4*>(&out[((b * 24 + co) * OH + oh) * OH + ow0]) = o;
}

// ===========================================================================
// BatchNorm
// ===========================================================================
template <int L>
__global__ void bn_stats_kernel(const float* __restrict__ bg,
                                const float* __restrict__ bb) {
    constexpr int HW = (128 >> L) * (128 >> L);
    constexpr int N  = 64 * HW;
    const float* y = act_buf<L>();
    int c = blockIdx.x;
    int t = threadIdx.x;

    float s = 0.f, s2 = 0.f;
    for (int i = t; i < N; i += 256) {
        int b = i / HW;
        int p = i - b * HW;
        float v = y[(b * 24 + c) * HW + p];
        s += v;
        s2 += v * v;
    }
    __shared__ float rs[256], rq[256];
    rs[t] = s;
    rq[t] = s2;
    __syncthreads();
    for (int o = 128; o > 0; o >>= 1) {
        if (t < o) { rs[t] += rs[t + o]; rq[t] += rq[t + o]; }
        __syncthreads();
    }
    if (t == 0) {
        float m   = rs[0] / (float)N;
        float var = rq[0] / (float)N - m * m;
        float rst = rsqrtf(var + 1e-5f);
        g_scale[c] = rst * bg[c];
        g_shift[c] = bb[c] - m * rst * bg[c];
    }
}

template <int L>
__global__ void bn_apply_kernel() {
    constexpr int HW = (128 >> L) * (128 >> L);
    constexpr int TOTAL = 64 * 24 * HW;
    float* y = act_buf<L>();
    int idx = blockIdx.x * blockDim.x + threadIdx.x;
    if (idx >= TOTAL) return;
    int c = (idx / HW) % 24;
    y[idx] = fmaf(y[idx], g_scale[c], g_shift[c]);
}

// ===========================================================================
// u/v/qb projections
// ===========================================================================
__global__ void uv_kernel(const float* __restrict__ gw1) {
    int bp = blockIdx.x;
    int b  = bp >> 6;
    int p  = bp & 63;
    int t  = threadIdx.x;

    __shared__ float o[26];
    if (t < 24) o[t] = g_act4[(b * 24 + t) * 64 + p];
    else if (t == 24) o[24] = (float)(p >> 3);
    else if (t == 25) o[25] = (float)(p & 7);
    __syncthreads();

    float u = 0.f, v = 0.f;
#pragma unroll
    for (int c = 0; c < 26; c++) {
        float oc = o[c];
        u = fmaf(oc, gw1[c * 256 + t], u);
        v = fmaf(oc, gw1[(26 + c) * 256 + t], v);
    }
    g_u[bp * 256 + t] = u;
    g_v[bp * 256 + t] = v;
}

__global__ void qb_kernel(const float* __restrict__ qst,
                          const float* __restrict__ gw1,
                          const float* __restrict__ gb1) {
    int b = blockIdx.x;
    int t = threadIdx.x;
    __shared__ float q[11];
    if (t < 11) q[t] = qst[b * 11 + t];
    __syncthreads();
    float s = gb1[t];
#pragma unroll
    for (int k = 0; k < 11; k++) s = fmaf(q[k], gw1[(52 + k) * 256 + t], s);
    g_qb[b * 256 + t] = s;
}

// ===========================================================================
// W prep: transpose to [n][k] and split into fp16 hi/lo planes
// ===========================================================================
__global__ void prep_w_kernel(const float* __restrict__ w2,
                              const float* __restrict__ w3,
                              const float* __restrict__ w4) {
    __shared__ float tb[32][33];
    int L = blockIdx.z;
    const float* w = (L == 0) ? w2 : (L == 1) ? w3 : w4;
    int kb = blockIdx.y * 32, nb = blockIdx.x * 32;
#pragma unroll
    for (int i = 0; i < 4; i++)
        tb[threadIdx.y + 8 * i][threadIdx.x] = w[(kb + threadIdx.y + 8 * i) * 256 + nb + threadIdx.x];
    __syncthreads();
#pragma unroll
    for (int i = 0; i < 4; i++) {
        int n = nb + threadIdx.y + 8 * i;
        int k = kb + threadIdx.x;
        float x = tb[threadIdx.x][threadIdx.y + 8 * i];
        __half h = __float2half_rn(x);
        g_Wth[L][n * 256 + k] = h;
        g_Wtl[L][n * 256 + k] = __float2half_rn(x - __half2float(h));
    }
}

// ===========================================================================
// fp16 split GEMM:  Y[262144,256] = relu(X @ W + bias), 3 passes via
// mma.m16n8k16 (A0B0 + A1B0 + A0B1).  CTA 128x256, 8 warps (2M x 4N),
// warp 64x64, K-chunks of 32, double-buffered, ldmatrix.x4, cp.async.
//   MODE 0: X = relu(u+v+qb) on the fly -> h2 planes
//   MODE 1: X = h2 planes -> h3 planes
//   MODE 2: X = h3 planes -> fused 128-row column sums -> g_part
// ===========================================================================
static constexpr int APLANE = 8192, ASTAGE = 16384;         // A: [st][pl][128*64B]
static constexpr int BOFF = 32768, BPLANE = 16384, BSTAGE = 32768;
static constexpr int GEMM_SMEM = 98304;

template <int MODE>
__global__ void __launch_bounds__(256, 1) rn_gemm(const float* __restrict__ bias) {
    extern __shared__ char smem[];
    const uint32_t sb = smem_to_u32(smem);

    const int tid  = threadIdx.x;
    const int lane = tid & 31;
    const int wid  = tid >> 5;
    const int g    = lane >> 2;
    const int tig  = lane & 3;
    const int warpM = wid & 1;
    const int warpN = wid >> 1;          // 0..3
    const int m0 = blockIdx.x << 7;

    // ---- ldmatrix fragment offsets (byte, base-relative) ----
    uint32_t offA[4][2], offB[4][2];
    {
        int ra = (lane & 7) + ((lane >> 3) & 1) * 8;
        int ca = (lane >> 4) & 1;
#pragma unroll
        for (int i = 0; i < 4; i++)
#pragma unroll
            for (int ks = 0; ks < 2; ks++) {
                int row = warpM * 64 + i * 16 + ra;
                int ch  = 2 * ks + ca;
                offA[i][ks] = row * 64 + ((ch ^ ((row >> 1) & 3)) << 4);
            }
        int rb = (lane & 7) + ((lane >> 4) & 1) * 8;
        int cbs = (lane >> 3) & 1;
#pragma unroll
        for (int jp = 0; jp < 4; jp++)
#pragma unroll
            for (int ks = 0; ks < 2; ks++) {
                int row = warpN * 64 + jp * 16 + rb;
                int ch  = 2 * ks + cbs;
                offB[jp][ks] = BOFF + row * 64 + ((ch ^ ((row >> 1) & 3)) << 4);
            }
    }

    // ---- staging maps ----
    const int arow = tid >> 1, kh = tid & 1;   // MODE 0: row, 16-k half
    const float *up = nullptr, *vp = nullptr, *qp = nullptr;
    if constexpr (MODE == 0) {
        int rg = m0 + arow;
        int b = rg >> 12, ii = (rg >> 6) & 63, jj = rg & 63;
        up = g_u + ((b << 6) + jj) * 256;
        vp = g_v + ((b << 6) + ii) * 256;
        qp = g_qb + (b << 8);
    }
    const __half* Asrc = nullptr;              // MODE 1/2: cp.async plane
    if constexpr (MODE >= 1) {
        const __half* hi = (MODE == 1) ? g_h2h : g_h3h;
        const __half* lo = (MODE == 1) ? g_h2l : g_h3l;
        Asrc = ((tid >> 7) ? lo : hi) + (size_t)(m0 + (tid & 127)) * 256;
    }
    const __half* Bsrc = ((tid >> 7) ? g_Wtl[MODE] : g_Wth[MODE]);

    float acc[4][8][4];
#pragma unroll
    for (int i = 0; i < 4; i++)
#pragma unroll
        for (int j = 0; j < 8; j++)
#pragma unroll
            for (int e = 0; e < 4; e++) acc[i][j][e] = 0.f;

    float4 xs[4];   // MODE 0 A staging

    auto issue_chunk = [&](int kt, int st) {
        // B: thread -> plane (tid>>7), rows 2*(tid&127), +1, 4 chunks each
        int p = tid >> 7;
#pragma unroll
        for (int rr = 0; rr < 2; rr++) {
            int row = 2 * (tid & 127) + rr;
            const __half* src = Bsrc + row * 256 + kt * 32;
            uint32_t dbase = sb + BOFF + st * BSTAGE + p * BPLANE + row * 64;
            int rsw = (row >> 1) & 3;
#pragma unroll
            for (int c = 0; c < 4; c++)
                cp_async16(dbase + ((c ^ rsw) << 4), src + 8 * c);
        }
        if constexpr (MODE >= 1) {
            int rowa = tid & 127;
            const __half* src = Asrc + kt * 32;
            uint32_t dbase = sb + st * ASTAGE + p * APLANE + rowa * 64;
            int rsw = (rowa >> 1) & 3;
#pragma unroll
            for (int c = 0; c < 4; c++)
                cp_async16(dbase + ((c ^ rsw) << 4), src + 8 * c);
        }
        CP_COMMIT();
    };
    auto loadA = [&](int kt) {
        if constexpr (MODE == 0) {
            int k0 = kt * 32 + kh * 16;
#pragma unroll
            for (int q = 0; q < 4; q++) {
                float4 uu = *reinterpret_cast<const float4*>(up + k0 + 4 * q);
                float4 vv = *reinterpret_cast<const float4*>(vp + k0 + 4 * q);
                float4 qq = *reinterpret_cast<const float4*>(qp + k0 + 4 * q);
                float4 x;
                x.x = fmaxf(uu.x + vv.x + qq.x, 0.f);
                x.y = fmaxf(uu.y + vv.y + qq.y, 0.f);
                x.z = fmaxf(uu.z + vv.z + qq.z, 0.f);
                x.w = fmaxf(uu.w + vv.w + qq.w, 0.f);
                xs[q] = x;
            }
        }
    };
    auto storeA = [&](int st) {
        if constexpr (MODE == 0) {
            uint32_t ph[8], pl[8];
#pragma unroll
            for (int q = 0; q < 4; q++) {
                split2(xs[q].x, xs[q].y, ph[2 * q], pl[2 * q]);
                split2(xs[q].z, xs[q].w, ph[2 * q + 1], pl[2 * q + 1]);
            }
            int rsw = (arow >> 1) & 3;
            uint32_t base = st * ASTAGE + arow * 64;
            uint32_t o0 = base + (((2 * kh + 0) ^ rsw) << 4);
            uint32_t o1 = base + (((2 * kh + 1) ^ rsw) << 4);
            *reinterpret_cast<uint4*>(smem + o0) = make_uint4(ph[0], ph[1], ph[2], ph[3]);
            *reinterpret_cast<uint4*>(smem + o1) = make_uint4(ph[4], ph[5], ph[6], ph[7]);
            *reinterpret_cast<uint4*>(smem + APLANE + o0) = make_uint4(pl[0], pl[1], pl[2], pl[3]);
            *reinterpret_cast<uint4*>(smem + APLANE + o1) = make_uint4(pl[4], pl[5], pl[6], pl[7]);
        }
    };

    // prologue
    issue_chunk(0, 0);
    loadA(0);
    storeA(0);

    for (int kt = 0; kt < 8; kt++) {
        const int st = kt & 1;
        CP_WAIT0();
        __syncthreads();
        if (kt < 7) { issue_chunk(kt + 1, st ^ 1); loadA(kt + 1); }

#pragma unroll
        for (int ks = 0; ks < 2; ks++) {
            uint32_t ah[4][4], al[4][4];
#pragma unroll
            for (int i = 0; i < 4; i++) {
                ldx4(ah[i], sb + st * ASTAGE + offA[i][ks]);
                ldx4(al[i], sb + st * ASTAGE + APLANE + offA[i][ks]);
            }
#pragma unroll
            for (int jp = 0; jp < 4; jp++) {
                uint32_t bh[4], bl[4];
                ldx4(bh, sb + st * BSTAGE + offB[jp][ks]);
                ldx4(bl, sb + st * BSTAGE + BPLANE + offB[jp][ks]);
#pragma unroll
                for (int i = 0; i < 4; i++) {
                    mma16(acc[i][2 * jp],     ah[i], bh);
                    mma16(acc[i][2 * jp],     al[i], bh);
                    mma16(acc[i][2 * jp],     ah[i], bl);
                    mma16(acc[i][2 * jp + 1], ah[i], bh + 2);
                    mma16(acc[i][2 * jp + 1], al[i], bh + 2);
                    mma16(acc[i][2 * jp + 1], ah[i], bl + 2);
                }
            }
        }
        if (kt < 7) storeA(st ^ 1);
    }

    // ---- epilogue ----
    if constexpr (MODE < 2) {
        __half* Yh = (MODE == 0) ? g_h2h : g_h3h;
        __half* Yl = (MODE == 0) ? g_h2l : g_h3l;
#pragma unroll
        for (int j = 0; j < 8; j++) {
            int c = warpN * 64 + j * 8 + 2 * tig;
            float b0 = bias[c], b1 = bias[c + 1];
#pragma unroll
            for (int i = 0; i < 4; i++) {
                int r0 = m0 + warpM * 64 + i * 16 + g;
                float y00 = fmaxf(acc[i][j][0] + b0, 0.f);
                float y01 = fmaxf(acc[i][j][1] + b1, 0.f);
                float y10 = fmaxf(acc[i][j][2] + b0, 0.f);
                float y11 = fmaxf(acc[i][j][3] + b1, 0.f);
                uint32_t h, l;
                split2(y00, y01, h, l);
                *reinterpret_cast<uint32_t*>(&Yh[(size_t)r0 * 256 + c]) = h;
                *reinterpret_cast<uint32_t*>(&Yl[(size_t)r0 * 256 + c]) = l;
                split2(y10, y11, h, l);
                *reinterpret_cast<uint32_t*>(&Yh[(size_t)(r0 + 8) * 256 + c]) = h;
                *reinterpret_cast<uint32_t*>(&Yl[(size_t)(r0 + 8) * 256 + c]) = l;
            }
        }
    } else {
        __syncthreads();                      // reuse smem
        float* red = reinterpret_cast<float*>(smem);   // [2][256]
#pragma unroll
        for (int j = 0; j < 8; j++) {
            int c = warpN * 64 + j * 8 + 2 * tig;
            float b0 = bias[c], b1 = bias[c + 1];
            float s0 = 0.f, s1 = 0.f;
#pragma unroll
            for (int i = 0; i < 4; i++) {
                s0 += fmaxf(acc[i][j][0] + b0, 0.f) + fmaxf(acc[i][j][2] + b0, 0.f);
                s1 += fmaxf(acc[i][j][1] + b1, 0.f) + fmaxf(acc[i][j][3] + b1, 0.f);
            }
#pragma unroll
            for (int m = 4; m <= 16; m <<= 1) {
                s0 += __shfl_xor_sync(0xffffffffu, s0, m);
                s1 += __shfl_xor_sync(0xffffffffu, s1, m);
            }
            if (lane < 4) {
                red[warpM * 256 + warpN * 64 + j * 8 + 2 * lane]     = s0;
                red[warpM * 256 + warpN * 64 + j * 8 + 2 * lane + 1] = s1;
            }
        }
        __syncthreads();
        g_part[blockIdx.x * 256 + tid] = red[tid] + red[256 + tid];
    }
}

// g_gsum[b][n] = sum over the 32 row-blocks of batch b
__global__ void reduce_g_kernel() {
    int b = blockIdx.x;
    int t = threadIdx.x;
    float s = 0.f;
#pragma unroll
    for (int k = 0; k < 32; k++) s += g_part[(b * 32 + k) * 256 + t];
    g_gsum[b * 256 + t] = s;
}

// ===========================================================================
// f-layers + softmax
// ===========================================================================
__global__ void f_kernel(const float* __restrict__ fw1, const float* __restrict__ fb1,
                         const float* __restrict__ fw2, const float* __restrict__ fb2,
                         const float* __restrict__ fw3, const float* __restrict__ fb3,
                         float* __restrict__ out) {
    int b = blockIdx.x;
    int t = threadIdx.x;
    __shared__ float s0[256], s1[256];
    __shared__ float lg[10];

    s0[t] = g_gsum[b * 256 + t];
    __syncthreads();

    float a = fb1[t];
    for (int c = 0; c < 256; c++) a = fmaf(s0[c], fw1[c * 256 + t], a);
    s1[t] = fmaxf(a, 0.f);
    __syncthreads();

    a = fb2[t];
    for (int c = 0; c < 256; c++) a = fmaf(s1[c], fw2[c * 256 + t], a);
    __syncthreads();
    s0[t] = fmaxf(a, 0.f);
    __syncthreads();

    if (t < 10) {
        float z = fb3[t];
        for (int c = 0; c < 256; c++) z = fmaf(s0[c], fw3[c * 10 + t], z);
        lg[t] = z;
    }
    __syncthreads();
    if (t == 0) {
        float mx = lg[0];
#pragma unroll
        for (int i = 1; i < 10; i++) mx = fmaxf(mx, lg[i]);
        float e[10];
        float ssum = 0.f;
#pragma unroll
        for (int i = 0; i < 10; i++) { e[i] = expf(lg[i] - mx); ssum += e[i]; }
        float inv = 1.0f / ssum;
#pragma unroll
        for (int i = 0; i < 10; i++) out[b * 10 + i] = e[i] * inv;
    }
}

// ===========================================================================
// Launch
// ===========================================================================
extern "C" void kernel_launch(void* const* d_in, const int* in_sizes, int n_in,
                              void* d_out, int out_size) {
    (void)in_sizes; (void)n_in; (void)out_size;
    const float* img = (const float*)d_in[0];
    const float* qst = (const float*)d_in[1];
    const float* cw1 = (const float*)d_in[2];
    const float* cb1 = (const float*)d_in[3];
    const float* bg1 = (const float*)d_in[4];
    const float* bb1 = (const float*)d_in[5];
    const float* cw2 = (const float*)d_in[6];
    const float* cb2 = (const float*)d_in[7];
    const float* bg2 = (const float*)d_in[8];
    const float* bb2 = (const float*)d_in[9];
    const float* cw3 = (const float*)d_in[10];
    const float* cb3 = (const float*)d_in[11];
    const float* bg3 = (const float*)d_in[12];
    const float* bb3 = (const float*)d_in[13];
    const float* cw4 = (const float*)d_in[14];
    const float* cb4 = (const float*)d_in[15];
    const float* bg4 = (const float*)d_in[16];
    const float* bb4 = (const float*)d_in[17];
    const float* gw1 = (const float*)d_in[18];
    const float* gb1 = (const float*)d_in[19];
    const float* gw2 = (const float*)d_in[20];
    const float* gb2 = (const float*)d_in[21];
    const float* gw3 = (const float*)d_in[22];
    const float* gb3 = (const float*)d_in[23];
    const float* gw4 = (const float*)d_in[24];
    const float* gb4 = (const float*)d_in[25];
    const float* fw1 = (const float*)d_in[26];
    const float* fb1 = (const float*)d_in[27];
    const float* fw2 = (const float*)d_in[28];
    const float* fb2 = (const float*)d_in[29];
    const float* fw3 = (const float*)d_in[30];
    const float* fb3 = (const float*)d_in[31];
    float* out = (float*)d_out;

    static bool attr_done = false;
    if (!attr_done) {
        cudaFuncSetAttribute(rn_gemm<0>, cudaFuncAttributeMaxDynamicSharedMemorySize, GEMM_SMEM);
        cudaFuncSetAttribute(rn_gemm<1>, cudaFuncAttributeMaxDynamicSharedMemorySize, GEMM_SMEM);
        cudaFuncSetAttribute(rn_gemm<2>, cudaFuncAttributeMaxDynamicSharedMemorySize, GEMM_SMEM);
        attr_done = true;
    }

    // W prep (independent)
    prep_w_kernel<<<dim3(8, 8, 3), dim3(32, 8)>>>(gw2, gw3, gw4);

    // conv stack
    conv_kernel<1><<<(64 * 24 * 64 * 64 / 4) / 256, 256>>>(img, cw1, cb1);
    bn_stats_kernel<1><<<24, 256>>>(bg1, bb1);
    bn_apply_kernel<1><<<(64 * 24 * 64 * 64) / 256, 256>>>();

    conv_kernel<2><<<(64 * 24 * 32 * 32 / 4) / 256, 256>>>(img, cw2, cb2);
    bn_stats_kernel<2><<<24, 256>>>(bg2, bb2);
    bn_apply_kernel<2><<<(64 * 24 * 32 * 32) / 256, 256>>>();

    conv_kernel<3><<<(64 * 24 * 16 * 16 / 4) / 256, 256>>>(img, cw3, cb3);
    bn_stats_kernel<3><<<24, 256>>>(bg3, bb3);
    bn_apply_kernel<3><<<(64 * 24 * 16 * 16) / 256, 256>>>();

    conv_kernel<4><<<(64 * 24 * 8 * 8 / 4) / 256, 256>>>(img, cw4, cb4);
    bn_stats_kernel<4><<<24, 256>>>(bg4, bb4);
    bn_apply_kernel<4><<<(64 * 24 * 8 * 8) / 256, 256>>>();

    // projections
    uv_kernel<<<4096, 256>>>(gw1);
    qb_kernel<<<64, 256>>>(qst, gw1, gb1);

    // relation MLP on tensor cores (fp16 split, 3-pass)
    rn_gemm<0><<<2048, 256, GEMM_SMEM>>>(gb2);
    rn_gemm<1><<<2048, 256, GEMM_SMEM>>>(gb3);
    rn_gemm<2><<<2048, 256, GEMM_SMEM>>>(gb4);
    reduce_g_kernel<<<64, 256>>>();

    // f-layers + softmax
    f_kernel<<<64, 256>>>(fw1, fb1, fw2, fb2, fw3, fb3, out);
}

// round 6
// speedup vs baseline: 1.5359x; 1.0830x over previous
#include <cuda_runtime.h>
#include <cuda_fp16.h>
#include <stdint.h>

// ===========================================================================
// Helpers
// ===========================================================================
__device__ __forceinline__ uint32_t smem_to_u32(const void* p) {
    uint32_t a;
    asm("{ .reg .u64 t; cvta.to.shared.u64 t, %1; cvt.u32.u64 %0, t; }" : "=r"(a) : "l"(p));
    return a;
}
__device__ __forceinline__ void cp_async16(uint32_t saddr, const void* gptr) {
    asm volatile("cp.async.cg.shared.global [%0], [%1], 16;" :: "r"(saddr), "l"(gptr));
}
#define CP_COMMIT() asm volatile("cp.async.commit_group;" ::: "memory")
#define CP_WAIT0()  asm volatile("cp.async.wait_group 0;" ::: "memory")

__device__ __forceinline__ void ldx4(uint32_t* r, uint32_t addr) {
    asm volatile("ldmatrix.sync.aligned.m8n8.x4.shared.b16 {%0,%1,%2,%3}, [%4];"
                 : "=r"(r[0]), "=r"(r[1]), "=r"(r[2]), "=r"(r[3]) : "r"(addr));
}
__device__ __forceinline__ void mma16(float* d, const uint32_t* a, const uint32_t* b) {
    asm volatile(
        "mma.sync.aligned.m16n8k16.row.col.f32.f16.f16.f32 "
        "{%0,%1,%2,%3}, {%4,%5,%6,%7}, {%8,%9}, {%0,%1,%2,%3};"
        : "+f"(d[0]), "+f"(d[1]), "+f"(d[2]), "+f"(d[3])
        : "r"(a[0]), "r"(a[1]), "r"(a[2]), "r"(a[3]), "r"(b[0]), "r"(b[1]));
}
__device__ __forceinline__ void split2(float a, float b, uint32_t& hi, uint32_t& lo) {
    __half ha = __float2half_rn(a), hb = __float2half_rn(b);
    __half la = __float2half_rn(a - __half2float(ha));
    __half lb = __float2half_rn(b - __half2float(hb));
    __half2 h = __halves2half2(ha, hb), l = __halves2half2(la, lb);
    hi = *reinterpret_cast<uint32_t*>(&h);
    lo = *reinterpret_cast<uint32_t*>(&l);
}

// ===========================================================================
// Scratch (device globals only)
// ===========================================================================
__device__ float g_act1[64 * 24 * 64 * 64];
__device__ float g_act2[64 * 24 * 32 * 32];
__device__ float g_act3[64 * 24 * 16 * 16];
__device__ float g_act4[64 * 24 * 8 * 8];
__device__ float g_scale[24];
__device__ float g_shift[24];
__device__ float g_u[4096 * 256];
__device__ float g_v[4096 * 256];
__device__ float g_qb[64 * 256];
__device__ __half g_h2h[262144UL * 256], g_h2l[262144UL * 256];
__device__ __half g_h3h[262144UL * 256], g_h3l[262144UL * 256];
__device__ __half g_Wth[3][256 * 256];   // W^T hi plane, [n][k]
__device__ __half g_Wtl[3][256 * 256];   // W^T lo plane
__device__ float g_part[2048 * 256];
__device__ float g_gsum[64 * 256];

// ===========================================================================
// Conv (3x3, stride 2, pad 1) + bias + relu.  4-wide ow microtile.
// ===========================================================================
template <int L>
__device__ __forceinline__ float* act_buf() {
    if constexpr (L == 1) return g_act1;
    else if constexpr (L == 2) return g_act2;
    else if constexpr (L == 3) return g_act3;
    else return g_act4;
}

template <int L>
__global__ void conv_kernel(const float* __restrict__ img,
                            const float* __restrict__ w,
                            const float* __restrict__ cb) {
    constexpr int CIN = (L == 1) ? 3 : 24;
    constexpr int H   = 256 >> L;
    constexpr int OH  = 128 >> L;
    constexpr int OQ  = OH / 4;

    const float* in = (L == 1) ? img : act_buf<L - 1 + (L == 1 ? 1 : 0)>();
    float* out = act_buf<L>();

    int idx = blockIdx.x * blockDim.x + threadIdx.x;
    int ow0 = (idx % OQ) * 4;
    int r   = idx / OQ;
    int oh  = r % OH;
    r /= OH;
    int co = r % 24;
    int b  = r / 24;
    if (b >= 64) return;

    float s0 = cb[co], s1 = s0, s2 = s0, s3 = s0;
    const int iwb = ow0 * 2 - 1;

#pragma unroll
    for (int ci = 0; ci < CIN; ci++) {
        const float* ip = in + ((b * CIN + ci) * H) * H;
        const float* wp = w + (co * CIN + ci) * 9;
#pragma unroll
        for (int kh = 0; kh < 3; kh++) {
            int ih = oh * 2 - 1 + kh;
            if (ih < 0 || ih >= H) continue;
            const float* rp = ip + ih * H;
            float x[9];
#pragma unroll
            for (int t = 0; t < 9; t++) {
                int iw = iwb + t;
                x[t] = (iw >= 0 && iw < H) ? rp[iw] : 0.f;
            }
            float w0 = wp[kh * 3], w1 = wp[kh * 3 + 1], w2 = wp[kh * 3 + 2];
            s0 = fmaf(x[0], w0, fmaf(x[1], w1, fmaf(x[2], w2, s0)));
            s1 = fmaf(x[2], w0, fmaf(x[3], w1, fmaf(x[4], w2, s1)));
            s2 = fmaf(x[4], w0, fmaf(x[5], w1, fmaf(x[6], w2, s2)));
            s3 = fmaf(x[6], w0, fmaf(x[7], w1, fmaf(x[8], w2, s3)));
        }
    }
    float4 o;
    o.x = fmaxf(s0, 0.f); o.y = fmaxf(s1, 0.f);
    o.z = fmaxf(s2, 0.f); o.w = fmaxf(s3, 0.f);
    *reinterpret_cast<float4*>(&out[((b * 24 + co) * OH + oh) * OH + ow0]) = o;
}

// ===========================================================================
// BatchNorm
// ===========================================================================
template <int L>
__global__ void bn_stats_kernel(const float* __restrict__ bg,
                                const float* __restrict__ bb) {
    constexpr int HW = (128 >> L) * (128 >> L);
    constexpr int N  = 64 * HW;
    const float* y = act_buf<L>();
    int c = blockIdx.x;
    int t = threadIdx.x;

    float s = 0.f, s2 = 0.f;
    for (int i = t; i < N; i += 256) {
        int b = i / HW;
        int p = i - b * HW;
        float v = y[(b * 24 + c) * HW + p];
        s += v;
        s2 += v * v;
    }
    __shared__ float rs[256], rq[256];
    rs[t] = s;
    rq[t] = s2;
    __syncthreads();
    for (int o = 128; o > 0; o >>= 1) {
        if (t < o) { rs[t] += rs[t + o]; rq[t] += rq[t + o]; }
        __syncthreads();
    }
    if (t == 0) {
        float m   = rs[0] / (float)N;
        float var = rq[0] / (float)N - m * m;
        float rst = rsqrtf(var + 1e-5f);
        g_scale[c] = rst * bg[c];
        g_shift[c] = bb[c] - m * rst * bg[c];
    }
}

template <int L>
__global__ void bn_apply_kernel() {
    constexpr int HW = (128 >> L) * (128 >> L);
    constexpr int TOTAL = 64 * 24 * HW;
    float* y = act_buf<L>();
    int idx = blockIdx.x * blockDim.x + threadIdx.x;
    if (idx >= TOTAL) return;
    int c = (idx / HW) % 24;
    y[idx] = fmaf(y[idx], g_scale[c], g_shift[c]);
}

// ===========================================================================
// u/v/qb projections
// ===========================================================================
__global__ void uv_kernel(const float* __restrict__ gw1) {
    int bp = blockIdx.x;
    int b  = bp >> 6;
    int p  = bp & 63;
    int t  = threadIdx.x;

    __shared__ float o[26];
    if (t < 24) o[t] = g_act4[(b * 24 + t) * 64 + p];
    else if (t == 24) o[24] = (float)(p >> 3);
    else if (t == 25) o[25] = (float)(p & 7);
    __syncthreads();

    float u = 0.f, v = 0.f;
#pragma unroll
    for (int c = 0; c < 26; c++) {
        float oc = o[c];
        u = fmaf(oc, gw1[c * 256 + t], u);
        v = fmaf(oc, gw1[(26 + c) * 256 + t], v);
    }
    g_u[bp * 256 + t] = u;
    g_v[bp * 256 + t] = v;
}

__global__ void qb_kernel(const float* __restrict__ qst,
                          const float* __restrict__ gw1,
                          const float* __restrict__ gb1) {
    int b = blockIdx.x;
    int t = threadIdx.x;
    __shared__ float q[11];
    if (t < 11) q[t] = qst[b * 11 + t];
    __syncthreads();
    float s = gb1[t];
#pragma unroll
    for (int k = 0; k < 11; k++) s = fmaf(q[k], gw1[(52 + k) * 256 + t], s);
    g_qb[b * 256 + t] = s;
}

// ===========================================================================
// W prep: transpose to [n][k] and split into fp16 hi/lo planes
// ===========================================================================
__global__ void prep_w_kernel(const float* __restrict__ w2,
                              const float* __restrict__ w3,
                              const float* __restrict__ w4) {
    __shared__ float tb[32][33];
    int L = blockIdx.z;
    const float* w = (L == 0) ? w2 : (L == 1) ? w3 : w4;
    int kb = blockIdx.y * 32, nb = blockIdx.x * 32;
#pragma unroll
    for (int i = 0; i < 4; i++)
        tb[threadIdx.y + 8 * i][threadIdx.x] = w[(kb + threadIdx.y + 8 * i) * 256 + nb + threadIdx.x];
    __syncthreads();
#pragma unroll
    for (int i = 0; i < 4; i++) {
        int n = nb + threadIdx.y + 8 * i;
        int k = kb + threadIdx.x;
        float x = tb[threadIdx.x][threadIdx.y + 8 * i];
        __half h = __float2half_rn(x);
        g_Wth[L][n * 256 + k] = h;
        g_Wtl[L][n * 256 + k] = __float2half_rn(x - __half2float(h));
    }
}

// ===========================================================================
// fp16 split GEMM:  Y[262144,256] = relu(X @ W + bias), 3 passes via
// mma.m16n8k16 (A0B0 + A1B0 + A0B1).  CTA 128x256, 16 warps (2M x 8N),
// warp tile 64x32, K-chunks of 32, double-buffered, ldmatrix.x4, cp.async.
//   MODE 0: X = relu(u+v+qb) on the fly -> h2 planes
//   MODE 1: X = h2 planes -> h3 planes
//   MODE 2: X = h3 planes -> fused 128-row column sums -> g_part
// ===========================================================================
static constexpr int APLANE = 8192, ASTAGE = 16384;         // A: [st][pl][128*64B]
static constexpr int BOFF = 32768, BPLANE = 16384, BSTAGE = 32768;
static constexpr int GEMM_SMEM = 98304;
static constexpr int EROW = 528;                            // epilogue row stride (bytes)

template <int MODE>
__global__ void __launch_bounds__(512, 1) rn_gemm(const float* __restrict__ bias) {
    extern __shared__ char smem[];
    const uint32_t sb = smem_to_u32(smem);

    const int tid  = threadIdx.x;
    const int lane = tid & 31;
    const int wid  = tid >> 5;           // 0..15
    const int g    = lane >> 2;
    const int tig  = lane & 3;
    const int warpM = wid & 1;
    const int warpN = wid >> 1;          // 0..7
    const int m0 = blockIdx.x << 7;

    // ---- ldmatrix fragment offsets (bytes, stage-relative) ----
    uint32_t offA[4][2], offB[2][2];
    {
        int ra = (lane & 7) + ((lane >> 3) & 1) * 8;
        int ca = (lane >> 4) & 1;
#pragma unroll
        for (int i = 0; i < 4; i++)
#pragma unroll
            for (int ks = 0; ks < 2; ks++) {
                int row = warpM * 64 + i * 16 + ra;
                int ch  = 2 * ks + ca;
                offA[i][ks] = row * 64 + ((ch ^ ((row >> 1) & 3)) << 4);
            }
        int rb = (lane & 7) + ((lane >> 4) & 1) * 8;
        int cbs = (lane >> 3) & 1;
#pragma unroll
        for (int jp = 0; jp < 2; jp++)
#pragma unroll
            for (int ks = 0; ks < 2; ks++) {
                int row = warpN * 32 + jp * 16 + rb;
                int ch  = 2 * ks + cbs;
                offB[jp][ks] = BOFF + row * 64 + ((ch ^ ((row >> 1) & 3)) << 4);
            }
    }

    // ---- staging maps ----
    // MODE 0: A built on the fly. 4 threads per row, 8 k's each.
    const int arow = tid >> 2, kq = tid & 3;
    const float *up = nullptr, *vp = nullptr, *qp = nullptr;
    if constexpr (MODE == 0) {
        int rg = m0 + arow;
        int b = rg >> 12, ii = (rg >> 6) & 63, jj = rg & 63;
        up = g_u + ((b << 6) + jj) * 256;
        vp = g_v + ((b << 6) + ii) * 256;
        qp = g_qb + (b << 8);
    }
    // MODE >= 1: A planes via cp.async. plane = tid>>8, 2 threads/row, 32B each.
    const __half* Asrc = nullptr;
    if constexpr (MODE >= 1) {
        const __half* hi = (MODE == 1) ? g_h2h : g_h3h;
        const __half* lo = (MODE == 1) ? g_h2l : g_h3l;
        Asrc = ((tid >> 8) ? lo : hi) + (size_t)(m0 + ((tid & 255) >> 1)) * 256;
    }
    // B: plane = tid>>8, one 64B row per thread.
    const __half* Bsrc = ((tid >> 8) ? g_Wtl[MODE] : g_Wth[MODE]);
    const int brow = tid & 255;

    float acc[4][4][4];
#pragma unroll
    for (int i = 0; i < 4; i++)
#pragma unroll
        for (int j = 0; j < 4; j++)
#pragma unroll
            for (int e = 0; e < 4; e++) acc[i][j][e] = 0.f;

    float4 xs[2];   // MODE 0 A staging (8 k values)

    auto issue_chunk = [&](int kt, int st) {
        int p = tid >> 8;
        {
            const __half* src = Bsrc + brow * 256 + kt * 32;
            uint32_t dbase = sb + BOFF + st * BSTAGE + p * BPLANE + brow * 64;
            int rsw = (brow >> 1) & 3;
#pragma unroll
            for (int c = 0; c < 4; c++)
                cp_async16(dbase + ((c ^ rsw) << 4), src + 8 * c);
        }
        if constexpr (MODE >= 1) {
            int row  = (tid & 255) >> 1;
            int half = tid & 1;
            const __half* src = Asrc + kt * 32;
            uint32_t dbase = sb + st * ASTAGE + p * APLANE + row * 64;
            int rsw = (row >> 1) & 3;
#pragma unroll
            for (int cc = 0; cc < 2; cc++) {
                int c = 2 * half + cc;
                cp_async16(dbase + ((c ^ rsw) << 4), src + 8 * c);
            }
        }
        CP_COMMIT();
    };
    auto loadA = [&](int kt) {
        if constexpr (MODE == 0) {
            int k0 = kt * 32 + kq * 8;
#pragma unroll
            for (int q = 0; q < 2; q++) {
                float4 uu = *reinterpret_cast<const float4*>(up + k0 + 4 * q);
                float4 vv = *reinterpret_cast<const float4*>(vp + k0 + 4 * q);
                float4 qq = *reinterpret_cast<const float4*>(qp + k0 + 4 * q);
                float4 x;
                x.x = fmaxf(uu.x + vv.x + qq.x, 0.f);
                x.y = fmaxf(uu.y + vv.y + qq.y, 0.f);
                x.z = fmaxf(uu.z + vv.z + qq.z, 0.f);
                x.w = fmaxf(uu.w + vv.w + qq.w, 0.f);
                xs[q] = x;
            }
        }
    };
    auto storeA = [&](int st) {
        if constexpr (MODE == 0) {
            uint32_t ph[4], pl[4];
            split2(xs[0].x, xs[0].y, ph[0], pl[0]);
            split2(xs[0].z, xs[0].w, ph[1], pl[1]);
            split2(xs[1].x, xs[1].y, ph[2], pl[2]);
            split2(xs[1].z, xs[1].w, ph[3], pl[3]);
            int rsw = (arow >> 1) & 3;
            uint32_t off = st * ASTAGE + arow * 64 + ((kq ^ rsw) << 4);
            *reinterpret_cast<uint4*>(smem + off) = make_uint4(ph[0], ph[1], ph[2], ph[3]);
            *reinterpret_cast<uint4*>(smem + APLANE + off) = make_uint4(pl[0], pl[1], pl[2], pl[3]);
        }
    };

    // prologue
    issue_chunk(0, 0);
    loadA(0);
    storeA(0);

    for (int kt = 0; kt < 8; kt++) {
        const int st = kt & 1;
        CP_WAIT0();
        __syncthreads();
        if (kt < 7) { issue_chunk(kt + 1, st ^ 1); loadA(kt + 1); }

#pragma unroll
        for (int ks = 0; ks < 2; ks++) {
            uint32_t bh[2][4], bl[2][4];
#pragma unroll
            for (int jp = 0; jp < 2; jp++) {
                ldx4(bh[jp], sb + st * BSTAGE + offB[jp][ks]);
                ldx4(bl[jp], sb + st * BSTAGE + BPLANE + offB[jp][ks]);
            }
#pragma unroll
            for (int i = 0; i < 4; i++) {
                uint32_t ah[4], al[4];
                ldx4(ah, sb + st * ASTAGE + offA[i][ks]);
                ldx4(al, sb + st * ASTAGE + APLANE + offA[i][ks]);
#pragma unroll
                for (int jp = 0; jp < 2; jp++) {
                    mma16(acc[i][2 * jp],     ah, bh[jp]);
                    mma16(acc[i][2 * jp],     al, bh[jp]);
                    mma16(acc[i][2 * jp],     ah, bl[jp]);
                    mma16(acc[i][2 * jp + 1], ah, bh[jp] + 2);
                    mma16(acc[i][2 * jp + 1], al, bh[jp] + 2);
                    mma16(acc[i][2 * jp + 1], ah, bl[jp] + 2);
                }
            }
        }
        if (kt < 7) storeA(st ^ 1);
    }

    // ---- bias for this thread's columns ----
    float bz[4][2];
#pragma unroll
    for (int j = 0; j < 4; j++) {
        int c = warpN * 32 + j * 8 + 2 * tig;
        bz[j][0] = bias[c];
        bz[j][1] = bias[c + 1];
    }

    if constexpr (MODE < 2) {
        __half* Yh = (MODE == 0) ? g_h2h : g_h3h;
        __half* Yl = (MODE == 0) ? g_h2l : g_h3l;
        __half* Yp[2] = {Yh, Yl};
#pragma unroll
        for (int p = 0; p < 2; p++) {
            __syncthreads();   // smem free for reuse
#pragma unroll
            for (int i = 0; i < 4; i++) {
                int r0 = warpM * 64 + i * 16 + g;
#pragma unroll
                for (int j = 0; j < 4; j++) {
                    int cbyte = warpN * 64 + j * 16 + tig * 4;
                    float y00 = fmaxf(acc[i][j][0] + bz[j][0], 0.f);
                    float y01 = fmaxf(acc[i][j][1] + bz[j][1], 0.f);
                    float y10 = fmaxf(acc[i][j][2] + bz[j][0], 0.f);
                    float y11 = fmaxf(acc[i][j][3] + bz[j][1], 0.f);
                    uint32_t h, l;
                    split2(y00, y01, h, l);
                    *reinterpret_cast<uint32_t*>(smem + r0 * EROW + cbyte) = p ? l : h;
                    split2(y10, y11, h, l);
                    *reinterpret_cast<uint32_t*>(smem + (r0 + 8) * EROW + cbyte) = p ? l : h;
                }
            }
            __syncthreads();
            // coalesced copy out: 128 rows x 512B
#pragma unroll
            for (int it = 0; it < 8; it++) {
                int chunk = tid + it * 512;
                int row = chunk >> 5, c16 = chunk & 31;
                uint4 v = *reinterpret_cast<uint4*>(smem + row * EROW + c16 * 16);
                *reinterpret_cast<uint4*>(Yp[p] + (size_t)(m0 + row) * 256 + c16 * 8) = v;
            }
        }
    } else {
        __syncthreads();
        float* red = reinterpret_cast<float*>(smem);   // [2][256]
#pragma unroll
        for (int j = 0; j < 4; j++) {
            float s0 = 0.f, s1 = 0.f;
#pragma unroll
            for (int i = 0; i < 4; i++) {
                s0 += fmaxf(acc[i][j][0] + bz[j][0], 0.f) + fmaxf(acc[i][j][2] + bz[j][0], 0.f);
                s1 += fmaxf(acc[i][j][1] + bz[j][1], 0.f) + fmaxf(acc[i][j][3] + bz[j][1], 0.f);
            }
#pragma unroll
            for (int m = 4; m <= 16; m <<= 1) {
                s0 += __shfl_xor_sync(0xffffffffu, s0, m);
                s1 += __shfl_xor_sync(0xffffffffu, s1, m);
            }
            if (lane < 4) {
                red[warpM * 256 + warpN * 32 + j * 8 + 2 * lane]     = s0;
                red[warpM * 256 + warpN * 32 + j * 8 + 2 * lane + 1] = s1;
            }
        }
        __syncthreads();
        if (tid < 256)
            g_part[blockIdx.x * 256 + tid] = red[tid] + red[256 + tid];
    }
}

// g_gsum[b][n] = sum over the 32 row-blocks of batch b
__global__ void reduce_g_kernel() {
    int b = blockIdx.x;
    int t = threadIdx.x;
    float s = 0.f;
#pragma unroll
    for (int k = 0; k < 32; k++) s += g_part[(b * 32 + k) * 256 + t];
    g_gsum[b * 256 + t] = s;
}

// ===========================================================================
// f-layers + softmax
// ===========================================================================
__global__ void f_kernel(const float* __restrict__ fw1, const float* __restrict__ fb1,
                         const float* __restrict__ fw2, const float* __restrict__ fb2,
                         const float* __restrict__ fw3, const float* __restrict__ fb3,
                         float* __restrict__ out) {
    int b = blockIdx.x;
    int t = threadIdx.x;
    __shared__ float s0[256], s1[256];
    __shared__ float lg[10];

    s0[t] = g_gsum[b * 256 + t];
    __syncthreads();

    float a = fb1[t];
    for (int c = 0; c < 256; c++) a = fmaf(s0[c], fw1[c * 256 + t], a);
    s1[t] = fmaxf(a, 0.f);
    __syncthreads();

    a = fb2[t];
    for (int c = 0; c < 256; c++) a = fmaf(s1[c], fw2[c * 256 + t], a);
    __syncthreads();
    s0[t] = fmaxf(a, 0.f);
    __syncthreads();

    if (t < 10) {
        float z = fb3[t];
        for (int c = 0; c < 256; c++) z = fmaf(s0[c], fw3[c * 10 + t], z);
        lg[t] = z;
    }
    __syncthreads();
    if (t == 0) {
        float mx = lg[0];
#pragma unroll
        for (int i = 1; i < 10; i++) mx = fmaxf(mx, lg[i]);
        float e[10];
        float ssum = 0.f;
#pragma unroll
        for (int i = 0; i < 10; i++) { e[i] = expf(lg[i] - mx); ssum += e[i]; }
        float inv = 1.0f / ssum;
#pragma unroll
        for (int i = 0; i < 10; i++) out[b * 10 + i] = e[i] * inv;
    }
}

// ===========================================================================
// Launch
// ===========================================================================
extern "C" void kernel_launch(void* const* d_in, const int* in_sizes, int n_in,
                              void* d_out, int out_size) {
    (void)in_sizes; (void)n_in; (void)out_size;
    const float* img = (const float*)d_in[0];
    const float* qst = (const float*)d_in[1];
    const float* cw1 = (const float*)d_in[2];
    const float* cb1 = (const float*)d_in[3];
    const float* bg1 = (const float*)d_in[4];
    const float* bb1 = (const float*)d_in[5];
    const float* cw2 = (const float*)d_in[6];
    const float* cb2 = (const float*)d_in[7];
    const float* bg2 = (const float*)d_in[8];
    const float* bb2 = (const float*)d_in[9];
    const float* cw3 = (const float*)d_in[10];
    const float* cb3 = (const float*)d_in[11];
    const float* bg3 = (const float*)d_in[12];
    const float* bb3 = (const float*)d_in[13];
    const float* cw4 = (const float*)d_in[14];
    const float* cb4 = (const float*)d_in[15];
    const float* bg4 = (const float*)d_in[16];
    const float* bb4 = (const float*)d_in[17];
    const float* gw1 = (const float*)d_in[18];
    const float* gb1 = (const float*)d_in[19];
    const float* gw2 = (const float*)d_in[20];
    const float* gb2 = (const float*)d_in[21];
    const float* gw3 = (const float*)d_in[22];
    const float* gb3 = (const float*)d_in[23];
    const float* gw4 = (const float*)d_in[24];
    const float* gb4 = (const float*)d_in[25];
    const float* fw1 = (const float*)d_in[26];
    const float* fb1 = (const float*)d_in[27];
    const float* fw2 = (const float*)d_in[28];
    const float* fb2 = (const float*)d_in[29];
    const float* fw3 = (const float*)d_in[30];
    const float* fb3 = (const float*)d_in[31];
    float* out = (float*)d_out;

    static bool attr_done = false;
    if (!attr_done) {
        cudaFuncSetAttribute(rn_gemm<0>, cudaFuncAttributeMaxDynamicSharedMemorySize, GEMM_SMEM);
        cudaFuncSetAttribute(rn_gemm<1>, cudaFuncAttributeMaxDynamicSharedMemorySize, GEMM_SMEM);
        cudaFuncSetAttribute(rn_gemm<2>, cudaFuncAttributeMaxDynamicSharedMemorySize, GEMM_SMEM);
        attr_done = true;
    }

    // W prep (independent)
    prep_w_kernel<<<dim3(8, 8, 3), dim3(32, 8)>>>(gw2, gw3, gw4);

    // conv stack
    conv_kernel<1><<<(64 * 24 * 64 * 64 / 4) / 256, 256>>>(img, cw1, cb1);
    bn_stats_kernel<1><<<24, 256>>>(bg1, bb1);
    bn_apply_kernel<1><<<(64 * 24 * 64 * 64) / 256, 256>>>();

    conv_kernel<2><<<(64 * 24 * 32 * 32 / 4) / 256, 256>>>(img, cw2, cb2);
    bn_stats_kernel<2><<<24, 256>>>(bg2, bb2);
    bn_apply_kernel<2><<<(64 * 24 * 32 * 32) / 256, 256>>>();

    conv_kernel<3><<<(64 * 24 * 16 * 16 / 4) / 256, 256>>>(img, cw3, cb3);
    bn_stats_kernel<3><<<24, 256>>>(bg3, bb3);
    bn_apply_kernel<3><<<(64 * 24 * 16 * 16) / 256, 256>>>();

    conv_kernel<4><<<(64 * 24 * 8 * 8 / 4) / 256, 256>>>(img, cw4, cb4);
    bn_stats_kernel<4><<<24, 256>>>(bg4, bb4);
    bn_apply_kernel<4><<<(64 * 24 * 8 * 8) / 256, 256>>>();

    // projections
    uv_kernel<<<4096, 256>>>(gw1);
    qb_kernel<<<64, 256>>>(qst, gw1, gb1);

    // relation MLP on tensor cores (fp16 split, 3-pass)
    rn_gemm<0><<<2048, 512, GEMM_SMEM>>>(gb2);
    rn_gemm<1><<<2048, 512, GEMM_SMEM>>>(gb3);
    rn_gemm<2><<<2048, 512, GEMM_SMEM>>>(gb4);
    reduce_g_kernel<<<64, 256>>>();

    // f-layers + softmax
    f_kernel<<<64, 256>>>(fw1, fb1, fw2, fb2, fw3, fb3, out);
}